// round 9
// baseline (speedup 1.0000x reference)
#include <cuda_runtime.h>
#include <stdint.h>

#define D_    1024
#define H_    768
#define HS_   1536
#define E_    8
#define TMAX  2048
#define AMAX  (TMAX*2)

// ---- int8 GEMM tile: CTA 128 x 64, K staged by 64 bytes ----
#define STRB   80                    // padded smem row stride (64B payload)
#define A_MATB (128*STRB)            // 10240
#define B_MATB (64*STRB)             // 5120
#define STAGEB (2*A_MATB+2*B_MATB)   // 30720
#define DYN    (2*STAGEB)            // 61440

// ---------------- routing scratch ----------------
__device__ int   g_counts[E_];
__device__ int   g_offs[E_ + 1];
__device__ int   g_cursor[E_];
__device__ int   g_top[AMAX];
__device__ float g_wgt[AMAX];
__device__ int   g_bucket[AMAX];
__device__ float g_bw[AMAX];

// ---------------- int8 two-plane operands + per-row scales ----------------
__device__ __align__(16) signed char g_x1[TMAX * D_],         g_x0[TMAX * D_];
__device__ float g_xsc[TMAX];
__device__ __align__(16) signed char g_W11[E_ * 2 * H_ * D_], g_W10[E_ * 2 * H_ * D_];
__device__ float g_W1sc[E_ * 2 * H_];
__device__ __align__(16) signed char g_W21[E_ * D_ * H_],     g_W20[E_ * D_ * H_];
__device__ float g_W2sc[E_ * D_];
__device__ __align__(16) signed char g_S11[2 * HS_ * D_],     g_S10[2 * HS_ * D_];
__device__ float g_S1sc[2 * HS_];
__device__ __align__(16) signed char g_S21[D_ * HS_],         g_S20[D_ * HS_];
__device__ float g_S2sc[D_];
// fp32 activations from fc1 + their quantized planes
__device__ __align__(16) float       g_actR[AMAX * H_];
__device__ __align__(16) signed char g_aR1[AMAX * H_],        g_aR0[AMAX * H_];
__device__ float g_aRsc[AMAX];
__device__ __align__(16) float       g_actS[TMAX * HS_];
__device__ __align__(16) signed char g_aS1[TMAX * HS_],       g_aS0[TMAX * HS_];
__device__ float g_aSsc[TMAX];

// ---------------- PTX helpers ----------------
__device__ __forceinline__ uint32_t cvta_s(const void* p) {
    return (uint32_t)__cvta_generic_to_shared(p);
}
#define CPA(dst, src) asm volatile("cp.async.cg.shared.global [%0], [%1], 16;\n" :: "r"(dst), "l"(src))
#define CPC()  asm volatile("cp.async.commit_group;\n")
#define CPW1() asm volatile("cp.async.wait_group 1;\n")
#define CPW0() asm volatile("cp.async.wait_group 0;\n")
#define LDM4(r0, r1, r2, r3, a) \
    asm volatile("ldmatrix.sync.aligned.m8n8.x4.shared.b16 {%0,%1,%2,%3}, [%4];" \
        : "=r"(r0), "=r"(r1), "=r"(r2), "=r"(r3) : "r"(a))
#define MMAI(c, a, b) \
    asm volatile("mma.sync.aligned.m16n8k32.row.col.s32.s8.s8.s32 " \
        "{%0,%1,%2,%3},{%4,%5,%6,%7},{%8,%9},{%0,%1,%2,%3};" \
        : "+r"(c[0]), "+r"(c[1]), "+r"(c[2]), "+r"(c[3]) \
        : "r"(a[0]), "r"(a[1]), "r"(a[2]), "r"(a[3]), "r"(b[0]), "r"(b[1]))

// ---------------- per-row int8 two-plane quantization ----------------
// v = s*(128*a1 + a0), s = absmax/16256, exact integer split, |a0|<=64.
struct QT { const float* src; signed char* p1; signed char* p0; float* sc; int rowlen; };
struct QArgs { QT t[5]; int ends[5]; int n; };

__global__ void k_quant(QArgs qa) {
    __shared__ float red[8];
    __shared__ float s_inv;
    int r = blockIdx.x;
    int i = 0;
    while (i < qa.n - 1 && r >= qa.ends[i]) i++;
    int lr = r - (i ? qa.ends[i - 1] : 0);
    QT t = qa.t[i];
    int L = t.rowlen;
    const float* row = t.src + (size_t)lr * L;
    int tid = threadIdx.x;
    int cnt = L >> 8;                              // 3, 4 or 6
    float v[6];
    float m = 0.f;
    for (int j = 0; j < cnt; j++) { v[j] = row[tid + (j << 8)]; m = fmaxf(m, fabsf(v[j])); }
#pragma unroll
    for (int o = 16; o; o >>= 1) m = fmaxf(m, __shfl_xor_sync(0xffffffffu, m, o));
    if ((tid & 31) == 0) red[tid >> 5] = m;
    __syncthreads();
    if (tid == 0) {
        float mm = red[0];
#pragma unroll
        for (int k = 1; k < 8; k++) mm = fmaxf(mm, red[k]);
        if (mm > 0.f) { t.sc[lr] = mm * (1.f / 16256.f); s_inv = 16256.f / mm; }
        else          { t.sc[lr] = 0.f;                  s_inv = 0.f; }
    }
    __syncthreads();
    float inv = s_inv;
    signed char* p1 = t.p1 + (size_t)lr * L;
    signed char* p0 = t.p0 + (size_t)lr * L;
    for (int j = 0; j < cnt; j++) {
        int iq = __float2int_rn(v[j] * inv);       // [-16256, 16256]
        int a1 = (iq + 64) >> 7;                   // [-127, 127]
        int a0 = iq - (a1 << 7);                   // [-64, 63]
        p1[tid + (j << 8)] = (signed char)a1;
        p0[tid + (j << 8)] = (signed char)a0;
    }
}

// ---------------- gate pipeline (fp32, proven R1/R2) ----------------
__global__ void k_zero() {
    if (threadIdx.x < E_) g_counts[threadIdx.x] = 0;
}

__global__ void k_gate(const float* __restrict__ x, const float* __restrict__ gw, int T) {
    __shared__ float sg[E_ * D_];
    const float4* gw4 = (const float4*)gw;
    float4* sg4 = (float4*)sg;
    for (int i = threadIdx.x; i < E_ * D_ / 4; i += blockDim.x) sg4[i] = gw4[i];
    __syncthreads();

    int wid = threadIdx.x >> 5, lane = threadIdx.x & 31;
    int t = blockIdx.x * 8 + wid;
    if (t >= T) return;

    float acc[E_];
#pragma unroll
    for (int e = 0; e < E_; e++) acc[e] = 0.f;
    const float4* xr = (const float4*)(x + (size_t)t * D_);
    for (int i = lane; i < D_ / 4; i += 32) {
        float4 xv = xr[i];
#pragma unroll
        for (int e = 0; e < E_; e++) {
            float4 g = sg4[e * (D_ / 4) + i];
            acc[e] += xv.x * g.x + xv.y * g.y + xv.z * g.z + xv.w * g.w;
        }
    }
#pragma unroll
    for (int e = 0; e < E_; e++)
#pragma unroll
        for (int o = 16; o > 0; o >>= 1) acc[e] += __shfl_xor_sync(0xffffffffu, acc[e], o);

    if (lane == 0) {
        float m = acc[0];
#pragma unroll
        for (int e = 1; e < E_; e++) m = fmaxf(m, acc[e]);
        float p[E_]; float s = 0.f;
#pragma unroll
        for (int e = 0; e < E_; e++) { p[e] = __expf(acc[e] - m); s += p[e]; }
        float inv = 1.f / s;
#pragma unroll
        for (int e = 0; e < E_; e++) p[e] *= inv;
        int i0 = 0; float v0 = p[0];
#pragma unroll
        for (int e = 1; e < E_; e++) if (p[e] > v0) { v0 = p[e]; i0 = e; }
        int i1 = -1; float v1 = -1.f;
#pragma unroll
        for (int e = 0; e < E_; e++) if (e != i0 && p[e] > v1) { v1 = p[e]; i1 = e; }
        g_top[t * 2] = i0;  g_top[t * 2 + 1] = i1;
        g_wgt[t * 2] = v0;  g_wgt[t * 2 + 1] = v1;
        atomicAdd(&g_counts[i0], 1);
        atomicAdd(&g_counts[i1], 1);
    }
}

__global__ void k_offs() {
    if (threadIdx.x == 0) {
        int s = 0;
        for (int e = 0; e < E_; e++) { g_offs[e] = s; s += g_counts[e]; g_cursor[e] = 0; }
        g_offs[E_] = s;
    }
}

__global__ void k_scatter(int T) {
    int i = blockIdx.x * blockDim.x + threadIdx.x;
    if (i >= T * 2) return;
    int t = i >> 1;
    int e = g_top[i];
    int pos = atomicAdd(&g_cursor[e], 1);
    int idx = g_offs[e] + pos;
    g_bucket[idx] = t;
    g_bw[idx] = g_wgt[i];
}

// ======================================================================
// fc1 (merged routed + shared): int8 two-plane IMMA, CTA tile 128 rows x
// 32 features (64 interleaved y/g weight rows). SiLU fused; fp32 acts out.
// grid.y: [0,192) routed (e=zy/24, ytile=zy%24); [192,240) shared.
// ======================================================================
__global__ __launch_bounds__(256)
void k_fc1(const signed char* __restrict__ x1p, const signed char* __restrict__ x0p,
           const float* __restrict__ xsc,
           const signed char* __restrict__ W11p, const signed char* __restrict__ W10p,
           const float* __restrict__ W1scp,
           const signed char* __restrict__ S11p, const signed char* __restrict__ S10p,
           const float* __restrict__ S1scp, int T) {
    extern __shared__ __align__(128) char dyn[];
    __shared__ int   toks[128];
    __shared__ float sAs[128], sBs[64];

    int zy = blockIdx.y;
    bool routed = zy < 192;
    int e = routed ? (zy / 24) : 0;
    int ytile = routed ? (zy % 24) : (zy - 192);
    int hid = routed ? H_ : HS_;
    int n0f = ytile * 32;
    const signed char* B1 = routed ? W11p + (size_t)e * 2 * H_ * D_ : S11p;
    const signed char* B0 = routed ? W10p + (size_t)e * 2 * H_ * D_ : S10p;
    const float* Bsc = routed ? W1scp + e * 2 * H_ : S1scp;
    float* outAct;
    { float* aR; float* aS;
      asm("cvta.global.u64 %0, %1;" : "=l"(aR) : "l"(g_actR));
      asm("cvta.global.u64 %0, %1;" : "=l"(aS) : "l"(g_actS));
      outAct = routed ? aR : aS; }
    int rbase = routed ? g_offs[e] : 0;
    int mcount = routed ? (g_offs[e + 1] - rbase) : T;
    int m0 = blockIdx.x * 128;
    if (m0 >= mcount) return;

    int tid = threadIdx.x;
    if (tid < 128) {
        int r = m0 + tid; if (r > mcount - 1) r = mcount - 1;
        int tok = routed ? g_bucket[rbase + r] : r;
        toks[tid] = tok;
        sAs[tid] = xsc[tok];
        if (tid < 64) {
            int f = n0f + (tid >> 1);
            sBs[tid] = Bsc[(tid & 1) ? hid + f : f];
        }
    }
    __syncthreads();

    uint32_t db = cvta_s(dyn);
    const int K = D_;
    const int nst = K / 64;
    int wid = tid >> 5, lane = tid & 31, wm = wid >> 2, wn = wid & 3;

    auto load_stage = [&](int s) {
        uint32_t sb = db + (uint32_t)(s & 1) * STAGEB;
        int k0 = s * 64;
#pragma unroll
        for (int j = 0; j < 6; j++) {
            int c = tid + 256 * j;
            uint32_t dst;
            const signed char* src;
            if (c < 1024) {                        // A planes (a1 then a0)
                int half = c >> 9, idx = c & 511;
                int row = idx >> 2, ch = idx & 3;
                dst = sb + (uint32_t)(half * A_MATB + row * STRB + ch * 16);
                src = (half ? x0p : x1p) + (size_t)toks[row] * K + k0 + ch * 16;
            } else {                               // B planes (b1 then b0)
                int cc = c - 1024;
                int half = cc >> 8, idx = cc & 255;
                int row = idx >> 2, ch = idx & 3;
                dst = sb + (uint32_t)(2 * A_MATB + half * B_MATB + row * STRB + ch * 16);
                int f = n0f + (row >> 1);
                int srow = (row & 1) ? hid + f : f;
                src = (half ? B0 : B1) + (size_t)srow * K + k0 + ch * 16;
            }
            CPA(dst, src);
        }
        CPC();
    };

    int c1[4][2][4], c2[4][2][4];
#pragma unroll
    for (int a = 0; a < 4; a++)
#pragma unroll
        for (int b = 0; b < 2; b++)
#pragma unroll
            for (int d = 0; d < 4; d++) { c1[a][b][d] = 0; c2[a][b][d] = 0; }

    int arowb = (wm * 64 + (lane & 15)) * STRB + (lane >> 4) * 16;
    int g8 = lane >> 3, brin = lane & 7;

    load_stage(0);
    for (int s = 0; s < nst; s++) {
        if (s + 1 < nst) { load_stage(s + 1); CPW1(); } else { CPW0(); }
        __syncthreads();
        uint32_t sb = db + (uint32_t)(s & 1) * STAGEB;
#pragma unroll
        for (int ks = 0; ks < 2; ks++) {
            uint32_t a1f[4][4], a0f[4][4], b1f[2][2], b0f[2][2];
#pragma unroll
            for (int mi = 0; mi < 4; mi++) {
                uint32_t off = sb + (uint32_t)(arowb + mi * 16 * STRB + ks * 32);
                LDM4(a1f[mi][0], a1f[mi][1], a1f[mi][2], a1f[mi][3], off);
                LDM4(a0f[mi][0], a0f[mi][1], a0f[mi][2], a0f[mi][3], off + A_MATB);
            }
            {
                uint32_t off = sb + (uint32_t)(2 * A_MATB +
                    (wn * 16 + (g8 >> 1) * 8 + brin) * STRB + ks * 32 + (g8 & 1) * 16);
                uint32_t r0, r1, r2, r3;
                LDM4(r0, r1, r2, r3, off);
                b1f[0][0] = r0; b1f[0][1] = r1; b1f[1][0] = r2; b1f[1][1] = r3;
                LDM4(r0, r1, r2, r3, off + B_MATB);
                b0f[0][0] = r0; b0f[0][1] = r1; b0f[1][0] = r2; b0f[1][1] = r3;
            }
#pragma unroll
            for (int mi = 0; mi < 4; mi++)
#pragma unroll
                for (int nj = 0; nj < 2; nj++) MMAI(c1[mi][nj], a1f[mi], b1f[nj]);
#pragma unroll
            for (int mi = 0; mi < 4; mi++)
#pragma unroll
                for (int nj = 0; nj < 2; nj++) MMAI(c2[mi][nj], a1f[mi], b0f[nj]);
#pragma unroll
            for (int mi = 0; mi < 4; mi++)
#pragma unroll
                for (int nj = 0; nj < 2; nj++) MMAI(c2[mi][nj], a0f[mi], b1f[nj]);
        }
        __syncthreads();
    }

    int rrem = mcount - m0;
#pragma unroll
    for (int mi = 0; mi < 4; mi++)
#pragma unroll
        for (int half = 0; half < 2; half++) {
            int lrow = wm * 64 + mi * 16 + (lane >> 2) + half * 8;
            if (lrow < rrem) {
                float sa = sAs[lrow];
                size_t rb = (size_t)(rbase + m0 + lrow) * hid;
                int i0 = half * 2;
#pragma unroll
                for (int nj = 0; nj < 2; nj++) {
                    int bloc = wn * 16 + nj * 8 + (lane & 3) * 2;
                    float yv = sa * sBs[bloc] * 128.f *
                        fmaf((float)c1[mi][nj][i0], 128.f, (float)c2[mi][nj][i0]);
                    float gv = sa * sBs[bloc + 1] * 128.f *
                        fmaf((float)c1[mi][nj][i0 + 1], 128.f, (float)c2[mi][nj][i0 + 1]);
                    float av = yv * gv / (1.f + __expf(-gv));
                    outAct[rb + n0f + (bloc >> 1)] = av;
                }
            }
        }
}

// ======================================================================
// fc2: int8 two-plane IMMA, CTA tile 128 rows x 64 cols.
// ROUTED -> atomicAdd * routing weight; shared -> plain store.
// ======================================================================
template <bool ROUTED>
__global__ __launch_bounds__(256)
void k_fc2(const signed char* __restrict__ a1p, const signed char* __restrict__ a0p,
           const float* __restrict__ ascp,
           const signed char* __restrict__ w1p, const signed char* __restrict__ w0p,
           const float* __restrict__ wscp,
           float* __restrict__ out, int T, int K) {
    extern __shared__ __align__(128) char dyn[];
    __shared__ int   toks[128];
    __shared__ float sAs[128], sBs[64];
    __shared__ int   etok[128];
    __shared__ float ew[128];

    int mcount, rbase;
    const signed char *B1 = w1p, *B0 = w0p;
    const float* Bsc = wscp;
    if (ROUTED) {
        int e = blockIdx.z;
        rbase = g_offs[e];
        mcount = g_offs[e + 1] - rbase;
        B1 += (size_t)e * D_ * H_;
        B0 += (size_t)e * D_ * H_;
        Bsc += e * D_;
    } else { mcount = T; rbase = 0; }
    int m0 = blockIdx.x * 128;
    if (m0 >= mcount) return;
    int n0 = blockIdx.y * 64;

    int tid = threadIdx.x;
    if (tid < 128) {
        int r = m0 + tid; if (r > mcount - 1) r = mcount - 1;
        int arow = rbase + r;
        toks[tid] = arow;
        sAs[tid] = ascp[arow];
        if (tid < 64) sBs[tid] = Bsc[n0 + tid];
        if (ROUTED) { etok[tid] = g_bucket[arow]; ew[tid] = g_bw[arow]; }
    }
    __syncthreads();

    uint32_t db = cvta_s(dyn);
    const int nst = K / 64;
    int wid = tid >> 5, lane = tid & 31, wm = wid >> 2, wn = wid & 3;

    auto load_stage = [&](int s) {
        uint32_t sb = db + (uint32_t)(s & 1) * STAGEB;
        int k0 = s * 64;
#pragma unroll
        for (int j = 0; j < 6; j++) {
            int c = tid + 256 * j;
            uint32_t dst;
            const signed char* src;
            if (c < 1024) {
                int half = c >> 9, idx = c & 511;
                int row = idx >> 2, ch = idx & 3;
                dst = sb + (uint32_t)(half * A_MATB + row * STRB + ch * 16);
                src = (half ? a0p : a1p) + (size_t)toks[row] * K + k0 + ch * 16;
            } else {
                int cc = c - 1024;
                int half = cc >> 8, idx = cc & 255;
                int row = idx >> 2, ch = idx & 3;
                dst = sb + (uint32_t)(2 * A_MATB + half * B_MATB + row * STRB + ch * 16);
                src = (half ? B0 : B1) + (size_t)(n0 + row) * K + k0 + ch * 16;
            }
            CPA(dst, src);
        }
        CPC();
    };

    int c1[4][2][4], c2[4][2][4];
#pragma unroll
    for (int a = 0; a < 4; a++)
#pragma unroll
        for (int b = 0; b < 2; b++)
#pragma unroll
            for (int d = 0; d < 4; d++) { c1[a][b][d] = 0; c2[a][b][d] = 0; }

    int arowb = (wm * 64 + (lane & 15)) * STRB + (lane >> 4) * 16;
    int g8 = lane >> 3, brin = lane & 7;

    load_stage(0);
    for (int s = 0; s < nst; s++) {
        if (s + 1 < nst) { load_stage(s + 1); CPW1(); } else { CPW0(); }
        __syncthreads();
        uint32_t sb = db + (uint32_t)(s & 1) * STAGEB;
#pragma unroll
        for (int ks = 0; ks < 2; ks++) {
            uint32_t a1f[4][4], a0f[4][4], b1f[2][2], b0f[2][2];
#pragma unroll
            for (int mi = 0; mi < 4; mi++) {
                uint32_t off = sb + (uint32_t)(arowb + mi * 16 * STRB + ks * 32);
                LDM4(a1f[mi][0], a1f[mi][1], a1f[mi][2], a1f[mi][3], off);
                LDM4(a0f[mi][0], a0f[mi][1], a0f[mi][2], a0f[mi][3], off + A_MATB);
            }
            {
                uint32_t off = sb + (uint32_t)(2 * A_MATB +
                    (wn * 16 + (g8 >> 1) * 8 + brin) * STRB + ks * 32 + (g8 & 1) * 16);
                uint32_t r0, r1, r2, r3;
                LDM4(r0, r1, r2, r3, off);
                b1f[0][0] = r0; b1f[0][1] = r1; b1f[1][0] = r2; b1f[1][1] = r3;
                LDM4(r0, r1, r2, r3, off + B_MATB);
                b0f[0][0] = r0; b0f[0][1] = r1; b0f[1][0] = r2; b0f[1][1] = r3;
            }
#pragma unroll
            for (int mi = 0; mi < 4; mi++)
#pragma unroll
                for (int nj = 0; nj < 2; nj++) MMAI(c1[mi][nj], a1f[mi], b1f[nj]);
#pragma unroll
            for (int mi = 0; mi < 4; mi++)
#pragma unroll
                for (int nj = 0; nj < 2; nj++) MMAI(c2[mi][nj], a1f[mi], b0f[nj]);
#pragma unroll
            for (int mi = 0; mi < 4; mi++)
#pragma unroll
                for (int nj = 0; nj < 2; nj++) MMAI(c2[mi][nj], a0f[mi], b1f[nj]);
        }
        __syncthreads();
    }

    int rrem = mcount - m0;
#pragma unroll
    for (int mi = 0; mi < 4; mi++)
#pragma unroll
        for (int half = 0; half < 2; half++) {
            int lrow = wm * 64 + mi * 16 + (lane >> 2) + half * 8;
            if (lrow < rrem) {
                float sa = sAs[lrow];
                int i0 = half * 2;
#pragma unroll
                for (int nj = 0; nj < 2; nj++) {
                    int bloc = wn * 16 + nj * 8 + (lane & 3) * 2;
                    float v0 = sa * sBs[bloc] * 128.f *
                        fmaf((float)c1[mi][nj][i0], 128.f, (float)c2[mi][nj][i0]);
                    float v1 = sa * sBs[bloc + 1] * 128.f *
                        fmaf((float)c1[mi][nj][i0 + 1], 128.f, (float)c2[mi][nj][i0 + 1]);
                    if (ROUTED) {
                        int t = etok[lrow]; float w = ew[lrow];
                        float* base = out + (size_t)t * D_ + n0 + bloc;
                        atomicAdd(base, w * v0);
                        atomicAdd(base + 1, w * v1);
                    } else {
                        *(float2*)(out + (size_t)(m0 + lrow) * D_ + n0 + bloc) =
                            make_float2(v0, v1);
                    }
                }
            }
        }
}

// ---------------- launcher ----------------
extern "C" void kernel_launch(void* const* d_in, const int* in_sizes, int n_in,
                              void* d_out, int out_size) {
    const float* x   = (const float*)d_in[0];
    const float* gw  = (const float*)d_in[1];
    const float* W1  = (const float*)d_in[2];
    const float* W2  = (const float*)d_in[3];
    const float* Ws1 = (const float*)d_in[4];
    const float* Ws2 = (const float*)d_in[5];
    float* out = (float*)d_out;

    int T = in_sizes[0] / D_;
    if (T > TMAX) T = TMAX;

    signed char *x1, *x0, *W11, *W10, *W21, *W20, *S11, *S10, *S21, *S20;
    signed char *aR1, *aR0, *aS1, *aS0;
    float *xsc, *W1sc, *W2sc, *S1sc, *S2sc, *aRsc, *aSsc, *actR, *actS;
    cudaGetSymbolAddress((void**)&x1,  g_x1);  cudaGetSymbolAddress((void**)&x0,  g_x0);
    cudaGetSymbolAddress((void**)&W11, g_W11); cudaGetSymbolAddress((void**)&W10, g_W10);
    cudaGetSymbolAddress((void**)&W21, g_W21); cudaGetSymbolAddress((void**)&W20, g_W20);
    cudaGetSymbolAddress((void**)&S11, g_S11); cudaGetSymbolAddress((void**)&S10, g_S10);
    cudaGetSymbolAddress((void**)&S21, g_S21); cudaGetSymbolAddress((void**)&S20, g_S20);
    cudaGetSymbolAddress((void**)&aR1, g_aR1); cudaGetSymbolAddress((void**)&aR0, g_aR0);
    cudaGetSymbolAddress((void**)&aS1, g_aS1); cudaGetSymbolAddress((void**)&aS0, g_aS0);
    cudaGetSymbolAddress((void**)&xsc,  g_xsc);  cudaGetSymbolAddress((void**)&W1sc, g_W1sc);
    cudaGetSymbolAddress((void**)&W2sc, g_W2sc); cudaGetSymbolAddress((void**)&S1sc, g_S1sc);
    cudaGetSymbolAddress((void**)&S2sc, g_S2sc); cudaGetSymbolAddress((void**)&aRsc, g_aRsc);
    cudaGetSymbolAddress((void**)&aSsc, g_aSsc);
    cudaGetSymbolAddress((void**)&actR, g_actR); cudaGetSymbolAddress((void**)&actS, g_actS);

    cudaFuncSetAttribute(k_fc1,        cudaFuncAttributeMaxDynamicSharedMemorySize, DYN);
    cudaFuncSetAttribute(k_fc2<true>,  cudaFuncAttributeMaxDynamicSharedMemorySize, DYN);
    cudaFuncSetAttribute(k_fc2<false>, cudaFuncAttributeMaxDynamicSharedMemorySize, DYN);

    // quant pass 1: x + all weights
    QArgs q1;
    q1.t[0] = { x,   x1,  x0,  xsc,  D_  };
    q1.t[1] = { W1,  W11, W10, W1sc, D_  };
    q1.t[2] = { W2,  W21, W20, W2sc, H_  };
    q1.t[3] = { Ws1, S11, S10, S1sc, D_  };
    q1.t[4] = { Ws2, S21, S20, S2sc, HS_ };
    int rows1[5] = { T, E_ * 2 * H_, E_ * D_, 2 * HS_, D_ };
    int cum = 0;
    for (int i = 0; i < 5; i++) { cum += rows1[i]; q1.ends[i] = cum; }
    q1.n = 5;
    k_quant<<<cum, 256>>>(q1);

    // routing
    k_zero<<<1, 32>>>();
    k_gate<<<(T + 7) / 8, 256>>>(x, gw, T);
    k_offs<<<1, 32>>>();
    k_scatter<<<(T * 2 + 255) / 256, 256>>>(T);

    int mt = (T + 127) / 128;

    // fc1 merged: routed 192 y-tiles + shared 48 y-tiles
    k_fc1<<<dim3(mt, 240), 256, DYN>>>(x1, x0, xsc, W11, W10, W1sc, S11, S10, S1sc, T);

    // quant pass 2: activations (routed 2T rows of H, shared T rows of HS)
    QArgs q2;
    q2.t[0] = { actR, aR1, aR0, aRsc, H_  };
    q2.t[1] = { actS, aS1, aS0, aSsc, HS_ };
    q2.ends[0] = 2 * T; q2.ends[1] = 3 * T;
    q2.n = 2;
    k_quant<<<3 * T, 256>>>(q2);

    // fc2: shared stores first, routed atomics after (stream-ordered)
    k_fc2<false><<<dim3(mt, D_ / 64),     256, DYN>>>(aS1, aS0, aSsc, S21, S20, S2sc, out, T, HS_);
    k_fc2<true ><<<dim3(mt, D_ / 64, E_), 256, DYN>>>(aR1, aR0, aRsc, W21, W20, W2sc, out, T, H_);
}

// round 10
// speedup vs baseline: 1.9732x; 1.9732x over previous
#include <cuda_runtime.h>
#include <cuda_bf16.h>
#include <stdint.h>

#define D_    1024
#define H_    768
#define HS_   1536
#define E_    8
#define TMAX  2048
#define AMAX  (TMAX*2)

#define KSZ   32
#define STR   40                      // smem row stride in bf16 elems (80B, conflict-free for ldmatrix)
#define STAGE_ELEMS (4*128*STR)       // Ah, Al, Bh, Bl tiles per stage
#define SMEM_BYTES  (2*STAGE_ELEMS*2) // 2 stages, 2B/elem = 81920

// ---------------- routing scratch ----------------
__device__ int   g_counts[E_];
__device__ int   g_offs[E_ + 1];
__device__ int   g_cursor[E_];
__device__ int   g_top[AMAX];
__device__ float g_wgt[AMAX];
__device__ int   g_bucket[AMAX];
__device__ float g_bw[AMAX];

// ---------------- bf16 hi/lo operand scratch ----------------
__device__ __align__(16) __nv_bfloat16 g_xh[TMAX * D_],         g_xl[TMAX * D_];
__device__ __align__(16) __nv_bfloat16 g_W1h[E_ * 2 * H_ * D_], g_W1l[E_ * 2 * H_ * D_];
__device__ __align__(16) __nv_bfloat16 g_W2h[E_ * D_ * H_],     g_W2l[E_ * D_ * H_];
__device__ __align__(16) __nv_bfloat16 g_S1h[2 * HS_ * D_],     g_S1l[2 * HS_ * D_];
__device__ __align__(16) __nv_bfloat16 g_S2h[D_ * HS_],         g_S2l[D_ * HS_];
__device__ __align__(16) __nv_bfloat16 g_aRh[AMAX * H_],        g_aRl[AMAX * H_];
__device__ __align__(16) __nv_bfloat16 g_aSh[TMAX * HS_],       g_aSl[TMAX * HS_];

// ---------------- PTX helpers ----------------
__device__ __forceinline__ uint32_t cvta_s(const void* p) {
    return (uint32_t)__cvta_generic_to_shared(p);
}
#define CPA(dst, src) asm volatile("cp.async.cg.shared.global [%0], [%1], 16;\n" :: "r"(dst), "l"(src))
#define CPC() asm volatile("cp.async.commit_group;\n")
#define CPW1() asm volatile("cp.async.wait_group 1;\n")
#define CPW0() asm volatile("cp.async.wait_group 0;\n")
#define LDM4(r0, r1, r2, r3, a) \
    asm volatile("ldmatrix.sync.aligned.m8n8.x4.shared.b16 {%0,%1,%2,%3}, [%4];" \
        : "=r"(r0), "=r"(r1), "=r"(r2), "=r"(r3) : "r"(a))
#define MMA(c, a, b) \
    asm volatile("mma.sync.aligned.m16n8k16.row.col.f32.bf16.bf16.f32 " \
        "{%0,%1,%2,%3},{%4,%5,%6,%7},{%8,%9},{%0,%1,%2,%3};" \
        : "+f"(c[0]), "+f"(c[1]), "+f"(c[2]), "+f"(c[3]) \
        : "r"(a[0]), "r"(a[1]), "r"(a[2]), "r"(a[3]), "r"(b[0]), "r"(b[1]))

// ---------------- fused conversion: all five fp32 tensors -> bf16 hi/lo ----------------
struct CvtArgs {
    const float* s[5];
    __nv_bfloat16* h[5];
    __nv_bfloat16* l[5];
    int bend[5];   // cumulative block boundaries
};

__global__ void k_cvt_all(CvtArgs a) {
    int b = blockIdx.x;
    int i = 0;
    if (b >= a.bend[0]) i = 1;
    if (b >= a.bend[1]) i = 2;
    if (b >= a.bend[2]) i = 3;
    if (b >= a.bend[3]) i = 4;
    int lb = b - (i ? a.bend[i - 1] : 0);
    int idx = lb * 256 + threadIdx.x;          // index of 8-float chunk

    const float4* src = (const float4*)a.s[i];
    float4 v0 = src[idx * 2];
    float4 v1 = src[idx * 2 + 1];
    float f[8] = {v0.x, v0.y, v0.z, v0.w, v1.x, v1.y, v1.z, v1.w};
    uint32_t hp[4], lp[4];
#pragma unroll
    for (int p = 0; p < 4; p++) {
        uint32_t hh = 0, ll = 0;
#pragma unroll
        for (int j = 0; j < 2; j++) {
            float x = f[p * 2 + j];
            __nv_bfloat16 h = __float2bfloat16(x);
            __nv_bfloat16 l = __float2bfloat16(x - __bfloat162float(h));
            hh |= (uint32_t)__bfloat16_as_ushort(h) << (16 * j);
            ll |= (uint32_t)__bfloat16_as_ushort(l) << (16 * j);
        }
        hp[p] = hh; lp[p] = ll;
    }
    ((uint4*)a.h[i])[idx] = make_uint4(hp[0], hp[1], hp[2], hp[3]);
    ((uint4*)a.l[i])[idx] = make_uint4(lp[0], lp[1], lp[2], lp[3]);
}

// ---------------- gate pipeline (fp32, proven R1/R2) ----------------
__global__ void k_zero() {
    if (threadIdx.x < E_) g_counts[threadIdx.x] = 0;
}

__global__ void k_gate(const float* __restrict__ x, const float* __restrict__ gw, int T) {
    __shared__ float sg[E_ * D_];
    const float4* gw4 = (const float4*)gw;
    float4* sg4 = (float4*)sg;
    for (int i = threadIdx.x; i < E_ * D_ / 4; i += blockDim.x) sg4[i] = gw4[i];
    __syncthreads();

    int wid = threadIdx.x >> 5, lane = threadIdx.x & 31;
    int t = blockIdx.x * 8 + wid;
    if (t >= T) return;

    float acc[E_];
#pragma unroll
    for (int e = 0; e < E_; e++) acc[e] = 0.f;
    const float4* xr = (const float4*)(x + (size_t)t * D_);
    for (int i = lane; i < D_ / 4; i += 32) {
        float4 xv = xr[i];
#pragma unroll
        for (int e = 0; e < E_; e++) {
            float4 g = sg4[e * (D_ / 4) + i];
            acc[e] += xv.x * g.x + xv.y * g.y + xv.z * g.z + xv.w * g.w;
        }
    }
#pragma unroll
    for (int e = 0; e < E_; e++)
#pragma unroll
        for (int o = 16; o > 0; o >>= 1) acc[e] += __shfl_xor_sync(0xffffffffu, acc[e], o);

    if (lane == 0) {
        float m = acc[0];
#pragma unroll
        for (int e = 1; e < E_; e++) m = fmaxf(m, acc[e]);
        float p[E_]; float s = 0.f;
#pragma unroll
        for (int e = 0; e < E_; e++) { p[e] = __expf(acc[e] - m); s += p[e]; }
        float inv = 1.f / s;
#pragma unroll
        for (int e = 0; e < E_; e++) p[e] *= inv;
        int i0 = 0; float v0 = p[0];
#pragma unroll
        for (int e = 1; e < E_; e++) if (p[e] > v0) { v0 = p[e]; i0 = e; }
        int i1 = -1; float v1 = -1.f;
#pragma unroll
        for (int e = 0; e < E_; e++) if (e != i0 && p[e] > v1) { v1 = p[e]; i1 = e; }
        g_top[t * 2] = i0;  g_top[t * 2 + 1] = i1;
        g_wgt[t * 2] = v0;  g_wgt[t * 2 + 1] = v1;
        atomicAdd(&g_counts[i0], 1);
        atomicAdd(&g_counts[i1], 1);
    }
}

__global__ void k_offs() {
    if (threadIdx.x == 0) {
        int s = 0;
        for (int e = 0; e < E_; e++) { g_offs[e] = s; s += g_counts[e]; g_cursor[e] = 0; }
        g_offs[E_] = s;
    }
}

__global__ void k_scatter(int T) {
    int i = blockIdx.x * blockDim.x + threadIdx.x;
    if (i >= T * 2) return;
    int t = i >> 1;
    int e = g_top[i];
    int pos = atomicAdd(&g_cursor[e], 1);
    int idx = g_offs[e] + pos;
    g_bucket[idx] = t;
    g_bw[idx] = g_wgt[i];
}

// ======================================================================
// fc1: tiled bf16-split MMA, term-major issue order (dep distance 16).
// CTA computes 128 rows x 64 features (128 interleaved y/g weight rows);
// SiLU fused at epilogue, activations written as bf16 hi/lo.
// ======================================================================
template <bool ROUTED>
__global__ __launch_bounds__(256)
void k_fc1t(const __nv_bfloat16* __restrict__ Ahg, const __nv_bfloat16* __restrict__ Alg,
            const __nv_bfloat16* __restrict__ Whg, const __nv_bfloat16* __restrict__ Wlg,
            __nv_bfloat16* __restrict__ Oh, __nv_bfloat16* __restrict__ Ol,
            int T, int hid) {
    extern __shared__ __nv_bfloat16 sm[];
    __shared__ int toks[128];

    int mcount, rbase;
    const __nv_bfloat16 *Wh, *Wl;
    if (ROUTED) {
        int e = blockIdx.z;
        rbase = g_offs[e];
        mcount = g_offs[e + 1] - rbase;
        size_t wo = (size_t)e * 2 * hid * D_;
        Wh = Whg + wo; Wl = Wlg + wo;
    } else { mcount = T; rbase = 0; Wh = Whg; Wl = Wlg; }
    int m0 = blockIdx.x * 128;
    if (m0 >= mcount) return;
    int n0f = blockIdx.y * 64;
    int tid = threadIdx.x;

    if (tid < 128) {
        int r = m0 + tid; if (r > mcount - 1) r = mcount - 1;
        toks[tid] = ROUTED ? g_bucket[rbase + r] : r;
    }
    __syncthreads();

    uint32_t sbase = cvta_s(sm);
    const int K = D_;
    const int nst = K / KSZ;

    auto load_stage = [&](int s) {
        uint32_t sb = sbase + (uint32_t)(s & 1) * (STAGE_ELEMS * 2);
        int k0 = s * KSZ;
#pragma unroll
        for (int j = 0; j < 8; j++) {
            int c = tid + 256 * j;
            int mat = c >> 9;
            int rc = c & 511;
            int row = rc >> 2;
            int ch = rc & 3;
            uint32_t dst = sb + (uint32_t)(mat * 128 * STR + row * STR + ch * 8) * 2;
            const __nv_bfloat16* src;
            if (mat < 2) {
                const __nv_bfloat16* base = (mat == 0) ? Ahg : Alg;
                src = base + (size_t)toks[row] * K + k0 + ch * 8;
            } else {
                int f = n0f + (row >> 1);
                int srow = (row & 1) ? (hid + f) : f;
                const __nv_bfloat16* base = (mat == 2) ? Wh : Wl;
                src = base + (size_t)srow * K + k0 + ch * 8;
            }
            CPA(dst, src);
        }
        CPC();
    };

    int wid = tid >> 5, lane = tid & 31;
    int wm = wid >> 2, wn = wid & 3;

    float c[4][4][4];
#pragma unroll
    for (int a = 0; a < 4; a++)
#pragma unroll
        for (int b = 0; b < 4; b++)
#pragma unroll
            for (int d = 0; d < 4; d++) c[a][b][d] = 0.f;

    int arow = wm * 64 + (lane & 15);
    int acol0 = (lane >> 4) * 8;
    int g8 = lane >> 3;
    int brin = lane & 7;

    load_stage(0);
    for (int s = 0; s < nst; s++) {
        if (s + 1 < nst) { load_stage(s + 1); CPW1(); } else { CPW0(); }
        __syncthreads();
        uint32_t sb = sbase + (uint32_t)(s & 1) * (STAGE_ELEMS * 2);
        uint32_t Ahb = sb;
        uint32_t Alb = sb + 128 * STR * 2;
        uint32_t Bhb = sb + 2 * 128 * STR * 2;
        uint32_t Blb = sb + 3 * 128 * STR * 2;
#pragma unroll
        for (int ks = 0; ks < 2; ks++) {
            uint32_t ah[4][4], al[4][4], bh[4][2], bl[4][2];
#pragma unroll
            for (int mi = 0; mi < 4; mi++) {
                uint32_t off = (uint32_t)((arow + mi * 16) * STR + ks * 16 + acol0) * 2;
                LDM4(ah[mi][0], ah[mi][1], ah[mi][2], ah[mi][3], Ahb + off);
                LDM4(al[mi][0], al[mi][1], al[mi][2], al[mi][3], Alb + off);
            }
#pragma unroll
            for (int j2 = 0; j2 < 2; j2++) {
                int nf = j2 * 2 + (g8 >> 1);
                uint32_t off = (uint32_t)((wn * 32 + nf * 8 + brin) * STR + ks * 16 + (g8 & 1) * 8) * 2;
                uint32_t r0, r1, r2, r3;
                LDM4(r0, r1, r2, r3, Bhb + off);
                bh[j2 * 2][0] = r0; bh[j2 * 2][1] = r1; bh[j2 * 2 + 1][0] = r2; bh[j2 * 2 + 1][1] = r3;
                LDM4(r0, r1, r2, r3, Blb + off);
                bl[j2 * 2][0] = r0; bl[j2 * 2][1] = r1; bl[j2 * 2 + 1][0] = r2; bl[j2 * 2 + 1][1] = r3;
            }
            // term-major: same-accumulator reuse distance = 16 MMAs
#pragma unroll
            for (int mi = 0; mi < 4; mi++)
#pragma unroll
                for (int nj = 0; nj < 4; nj++) MMA(c[mi][nj], ah[mi], bh[nj]);
#pragma unroll
            for (int mi = 0; mi < 4; mi++)
#pragma unroll
                for (int nj = 0; nj < 4; nj++) MMA(c[mi][nj], ah[mi], bl[nj]);
#pragma unroll
            for (int mi = 0; mi < 4; mi++)
#pragma unroll
                for (int nj = 0; nj < 4; nj++) MMA(c[mi][nj], al[mi], bh[nj]);
        }
        __syncthreads();
    }

    int rrem = mcount - m0;
#pragma unroll
    for (int mi = 0; mi < 4; mi++)
#pragma unroll
        for (int half = 0; half < 2; half++) {
            int row = wm * 64 + mi * 16 + (lane >> 2) + half * 8;
            if (row < rrem) {
                size_t rb = (size_t)(rbase + m0 + row) * hid;
#pragma unroll
                for (int nj = 0; nj < 4; nj++) {
                    float y = c[mi][nj][half * 2 + 0];
                    float g = c[mi][nj][half * 2 + 1];
                    float a = y * g / (1.f + __expf(-g));
                    int f = n0f + wn * 16 + nj * 4 + (lane & 3);
                    __nv_bfloat16 h = __float2bfloat16(a);
                    Oh[rb + f] = h;
                    Ol[rb + f] = __float2bfloat16(a - __bfloat162float(h));
                }
            }
        }
}

// ======================================================================
// fc2: 128x128 bf16-split GEMM tile, term-major issue order; routed rows
// combine via atomicAdd * routing weight, shared rows store directly.
// ======================================================================
template <bool ROUTED>
__global__ __launch_bounds__(256)
void k_fc2t(const __nv_bfloat16* __restrict__ Ahg, const __nv_bfloat16* __restrict__ Alg,
            const __nv_bfloat16* __restrict__ Whg, const __nv_bfloat16* __restrict__ Wlg,
            float* __restrict__ out, int T, int hid) {
    extern __shared__ __nv_bfloat16 sm[];
    __shared__ int toks[128];
    __shared__ float bws[128];

    int mcount, rbase;
    const __nv_bfloat16 *Wh, *Wl;
    if (ROUTED) {
        int e = blockIdx.z;
        rbase = g_offs[e];
        mcount = g_offs[e + 1] - rbase;
        size_t wo = (size_t)e * D_ * hid;
        Wh = Whg + wo; Wl = Wlg + wo;
    } else { mcount = T; rbase = 0; Wh = Whg; Wl = Wlg; }
    int m0 = blockIdx.x * 128;
    if (m0 >= mcount) return;
    int n0 = blockIdx.y * 128;
    int tid = threadIdx.x;

    if (ROUTED && tid < 128) {
        int r = m0 + tid; if (r > mcount - 1) r = mcount - 1;
        toks[tid] = g_bucket[rbase + r];
        bws[tid] = g_bw[rbase + r];
    }
    __syncthreads();

    uint32_t sbase = cvta_s(sm);
    const int K = hid;
    const int nst = K / KSZ;

    auto load_stage = [&](int s) {
        uint32_t sb = sbase + (uint32_t)(s & 1) * (STAGE_ELEMS * 2);
        int k0 = s * KSZ;
#pragma unroll
        for (int j = 0; j < 8; j++) {
            int c = tid + 256 * j;
            int mat = c >> 9;
            int rc = c & 511;
            int row = rc >> 2;
            int ch = rc & 3;
            uint32_t dst = sb + (uint32_t)(mat * 128 * STR + row * STR + ch * 8) * 2;
            const __nv_bfloat16* src;
            if (mat < 2) {
                int ar = m0 + row; if (ar > mcount - 1) ar = mcount - 1;
                const __nv_bfloat16* base = (mat == 0) ? Ahg : Alg;
                src = base + (size_t)(rbase + ar) * K + k0 + ch * 8;
            } else {
                const __nv_bfloat16* base = (mat == 2) ? Wh : Wl;
                src = base + (size_t)(n0 + row) * K + k0 + ch * 8;
            }
            CPA(dst, src);
        }
        CPC();
    };

    int wid = tid >> 5, lane = tid & 31;
    int wm = wid >> 2, wn = wid & 3;

    float c[4][4][4];
#pragma unroll
    for (int a = 0; a < 4; a++)
#pragma unroll
        for (int b = 0; b < 4; b++)
#pragma unroll
            for (int d = 0; d < 4; d++) c[a][b][d] = 0.f;

    int arow = wm * 64 + (lane & 15);
    int acol0 = (lane >> 4) * 8;
    int g8 = lane >> 3;
    int brin = lane & 7;

    load_stage(0);
    for (int s = 0; s < nst; s++) {
        if (s + 1 < nst) { load_stage(s + 1); CPW1(); } else { CPW0(); }
        __syncthreads();
        uint32_t sb = sbase + (uint32_t)(s & 1) * (STAGE_ELEMS * 2);
        uint32_t Ahb = sb;
        uint32_t Alb = sb + 128 * STR * 2;
        uint32_t Bhb = sb + 2 * 128 * STR * 2;
        uint32_t Blb = sb + 3 * 128 * STR * 2;
#pragma unroll
        for (int ks = 0; ks < 2; ks++) {
            uint32_t ah[4][4], al[4][4], bh[4][2], bl[4][2];
#pragma unroll
            for (int mi = 0; mi < 4; mi++) {
                uint32_t off = (uint32_t)((arow + mi * 16) * STR + ks * 16 + acol0) * 2;
                LDM4(ah[mi][0], ah[mi][1], ah[mi][2], ah[mi][3], Ahb + off);
                LDM4(al[mi][0], al[mi][1], al[mi][2], al[mi][3], Alb + off);
            }
#pragma unroll
            for (int j2 = 0; j2 < 2; j2++) {
                int nf = j2 * 2 + (g8 >> 1);
                uint32_t off = (uint32_t)((wn * 32 + nf * 8 + brin) * STR + ks * 16 + (g8 & 1) * 8) * 2;
                uint32_t r0, r1, r2, r3;
                LDM4(r0, r1, r2, r3, Bhb + off);
                bh[j2 * 2][0] = r0; bh[j2 * 2][1] = r1; bh[j2 * 2 + 1][0] = r2; bh[j2 * 2 + 1][1] = r3;
                LDM4(r0, r1, r2, r3, Blb + off);
                bl[j2 * 2][0] = r0; bl[j2 * 2][1] = r1; bl[j2 * 2 + 1][0] = r2; bl[j2 * 2 + 1][1] = r3;
            }
            // term-major: same-accumulator reuse distance = 16 MMAs
#pragma unroll
            for (int mi = 0; mi < 4; mi++)
#pragma unroll
                for (int nj = 0; nj < 4; nj++) MMA(c[mi][nj], ah[mi], bh[nj]);
#pragma unroll
            for (int mi = 0; mi < 4; mi++)
#pragma unroll
                for (int nj = 0; nj < 4; nj++) MMA(c[mi][nj], ah[mi], bl[nj]);
#pragma unroll
            for (int mi = 0; mi < 4; mi++)
#pragma unroll
                for (int nj = 0; nj < 4; nj++) MMA(c[mi][nj], al[mi], bh[nj]);
        }
        __syncthreads();
    }

    int rrem = mcount - m0;
#pragma unroll
    for (int mi = 0; mi < 4; mi++)
#pragma unroll
        for (int half = 0; half < 2; half++) {
            int row = wm * 64 + mi * 16 + (lane >> 2) + half * 8;
            if (row < rrem) {
#pragma unroll
                for (int nj = 0; nj < 4; nj++) {
                    int col = n0 + wn * 32 + nj * 8 + (lane & 3) * 2;
                    float v0 = c[mi][nj][half * 2 + 0];
                    float v1 = c[mi][nj][half * 2 + 1];
                    if (ROUTED) {
                        int t = toks[row]; float w = bws[row];
                        atomicAdd(out + (size_t)t * D_ + col, w * v0);
                        atomicAdd(out + (size_t)t * D_ + col + 1, w * v1);
                    } else {
                        *(float2*)(out + (size_t)(m0 + row) * D_ + col) = make_float2(v0, v1);
                    }
                }
            }
        }
}

// ---------------- launcher ----------------
extern "C" void kernel_launch(void* const* d_in, const int* in_sizes, int n_in,
                              void* d_out, int out_size) {
    const float* x   = (const float*)d_in[0];
    const float* gw  = (const float*)d_in[1];
    const float* W1  = (const float*)d_in[2];
    const float* W2  = (const float*)d_in[3];
    const float* Ws1 = (const float*)d_in[4];
    const float* Ws2 = (const float*)d_in[5];
    float* out = (float*)d_out;

    int T = in_sizes[0] / D_;
    if (T > TMAX) T = TMAX;

    __nv_bfloat16 *xh, *xl, *W1h, *W1l, *W2h, *W2l, *S1h, *S1l, *S2h, *S2l, *aRh, *aRl, *aSh, *aSl;
    cudaGetSymbolAddress((void**)&xh,  g_xh);  cudaGetSymbolAddress((void**)&xl,  g_xl);
    cudaGetSymbolAddress((void**)&W1h, g_W1h); cudaGetSymbolAddress((void**)&W1l, g_W1l);
    cudaGetSymbolAddress((void**)&W2h, g_W2h); cudaGetSymbolAddress((void**)&W2l, g_W2l);
    cudaGetSymbolAddress((void**)&S1h, g_S1h); cudaGetSymbolAddress((void**)&S1l, g_S1l);
    cudaGetSymbolAddress((void**)&S2h, g_S2h); cudaGetSymbolAddress((void**)&S2l, g_S2l);
    cudaGetSymbolAddress((void**)&aRh, g_aRh); cudaGetSymbolAddress((void**)&aRl, g_aRl);
    cudaGetSymbolAddress((void**)&aSh, g_aSh); cudaGetSymbolAddress((void**)&aSl, g_aSl);

    cudaFuncSetAttribute(k_fc1t<true>,  cudaFuncAttributeMaxDynamicSharedMemorySize, SMEM_BYTES);
    cudaFuncSetAttribute(k_fc1t<false>, cudaFuncAttributeMaxDynamicSharedMemorySize, SMEM_BYTES);
    cudaFuncSetAttribute(k_fc2t<true>,  cudaFuncAttributeMaxDynamicSharedMemorySize, SMEM_BYTES);
    cudaFuncSetAttribute(k_fc2t<false>, cudaFuncAttributeMaxDynamicSharedMemorySize, SMEM_BYTES);

    // fused conversion (single launch)
    CvtArgs ca;
    ca.s[0] = x;   ca.h[0] = xh;  ca.l[0] = xl;
    ca.s[1] = W1;  ca.h[1] = W1h; ca.l[1] = W1l;
    ca.s[2] = W2;  ca.h[2] = W2h; ca.l[2] = W2l;
    ca.s[3] = Ws1; ca.h[3] = S1h; ca.l[3] = S1l;
    ca.s[4] = Ws2; ca.h[4] = S2h; ca.l[4] = S2l;
    int nb[5] = {
        (T * D_ / 8) / 256,
        (E_ * 2 * H_ * D_ / 8) / 256,
        (E_ * D_ * H_ / 8) / 256,
        (2 * HS_ * D_ / 8) / 256,
        (D_ * HS_ / 8) / 256
    };
    int cum = 0;
    for (int i = 0; i < 5; i++) { cum += nb[i]; ca.bend[i] = cum; }
    k_cvt_all<<<cum, 256>>>(ca);

    // routing
    k_zero<<<1, 32>>>();
    k_gate<<<(T + 7) / 8, 256>>>(x, gw, T);
    k_offs<<<1, 32>>>();
    k_scatter<<<(T * 2 + 255) / 256, 256>>>(T);

    int mt = (T + 127) / 128;

    // fc1: routed (hidden 768) and shared (hidden 1536)
    k_fc1t<true ><<<dim3(mt, H_  / 64, E_), 256, SMEM_BYTES>>>(xh, xl, W1h, W1l, aRh, aRl, T, H_);
    k_fc1t<false><<<dim3(mt, HS_ / 64),     256, SMEM_BYTES>>>(xh, xl, S1h, S1l, aSh, aSl, T, HS_);

    // fc2: shared stores first, routed atomics after (stream-ordered)
    k_fc2t<false><<<dim3(mt, D_ / 128),     256, SMEM_BYTES>>>(aSh, aSl, S2h, S2l, out, T, HS_);
    k_fc2t<true ><<<dim3(mt, D_ / 128, E_), 256, SMEM_BYTES>>>(aRh, aRl, W2h, W2l, out, T, H_);
}

// round 11
// speedup vs baseline: 2.9565x; 1.4983x over previous
#include <cuda_runtime.h>
#include <cuda_fp16.h>
#include <stdint.h>

#define D_    1024
#define H_    768
#define HS_   1536
#define E_    8
#define TMAX  2048
#define AMAX  (TMAX*2)

#define KSZ   32
#define STR   40                      // smem row stride in fp16 elems (80B, conflict-free)
#define MATB  (128*STR*2)             // 10240 B per matrix tile (128 rows x 32 elems + pad)
#define STAGEB (3*MATB)               // A, Bh, Bl -> 30720 B
#define SMEM_BYTES (2*STAGEB)         // 61440 B, double buffered
#define WSCALE 256.f
#define INV_WSCALE (1.f/256.f)

// ---------------- routing scratch ----------------
__device__ int   g_counts[E_];
__device__ int   g_offs[E_ + 1];
__device__ int   g_cursor[E_];
__device__ int   g_top[AMAX];
__device__ float g_wgt[AMAX];
__device__ int   g_bucket[AMAX];
__device__ float g_bw[AMAX];

// ---------------- fp16 operand scratch ----------------
__device__ __align__(16) __half g_xq[TMAX * D_];                        // x, single plane
__device__ __align__(16) __half g_W1h[E_ * 2 * H_ * D_], g_W1l[E_ * 2 * H_ * D_];
__device__ __align__(16) __half g_W2h[E_ * D_ * H_],     g_W2l[E_ * D_ * H_];
__device__ __align__(16) __half g_S1h[2 * HS_ * D_],     g_S1l[2 * HS_ * D_];
__device__ __align__(16) __half g_S2h[D_ * HS_],         g_S2l[D_ * HS_];
__device__ __align__(16) __half g_aRq[AMAX * H_];                       // routed acts, single plane
__device__ __align__(16) __half g_aSq[TMAX * HS_];                      // shared acts, single plane

// ---------------- PTX helpers ----------------
__device__ __forceinline__ uint32_t cvta_s(const void* p) {
    return (uint32_t)__cvta_generic_to_shared(p);
}
#define CPA(dst, src) asm volatile("cp.async.cg.shared.global [%0], [%1], 16;\n" :: "r"(dst), "l"(src))
#define CPC() asm volatile("cp.async.commit_group;\n")
#define CPW1() asm volatile("cp.async.wait_group 1;\n")
#define CPW0() asm volatile("cp.async.wait_group 0;\n")
#define LDM4(r0, r1, r2, r3, a) \
    asm volatile("ldmatrix.sync.aligned.m8n8.x4.shared.b16 {%0,%1,%2,%3}, [%4];" \
        : "=r"(r0), "=r"(r1), "=r"(r2), "=r"(r3) : "r"(a))
#define MMA(c, a, b) \
    asm volatile("mma.sync.aligned.m16n8k16.row.col.f32.f16.f16.f32 " \
        "{%0,%1,%2,%3},{%4,%5,%6,%7},{%8,%9},{%0,%1,%2,%3};" \
        : "+f"(c[0]), "+f"(c[1]), "+f"(c[2]), "+f"(c[3]) \
        : "r"(a[0]), "r"(a[1]), "r"(a[2]), "r"(a[3]), "r"(b[0]), "r"(b[1]))

// ---------------- conversion: x -> single fp16; weights -> (256*w) hi/lo fp16 ----------------
struct CvtArgs {
    const float* s[5];
    __half* h[5];
    __half* l[5];      // nullptr -> single-plane mode (no scale)
    int bend[5];
};

__global__ void k_cvt_all(CvtArgs a) {
    int b = blockIdx.x;
    int i = 0;
    if (b >= a.bend[0]) i = 1;
    if (b >= a.bend[1]) i = 2;
    if (b >= a.bend[2]) i = 3;
    if (b >= a.bend[3]) i = 4;
    int lb = b - (i ? a.bend[i - 1] : 0);
    int idx = lb * 256 + threadIdx.x;          // index of 8-float chunk

    const float4* src = (const float4*)a.s[i];
    float4 v0 = src[idx * 2];
    float4 v1 = src[idx * 2 + 1];
    float f[8] = {v0.x, v0.y, v0.z, v0.w, v1.x, v1.y, v1.z, v1.w};
    if (a.l[i] == nullptr) {
        uint32_t hp[4];
#pragma unroll
        for (int p = 0; p < 4; p++) {
            __half h0 = __float2half_rn(f[p * 2]);
            __half h1 = __float2half_rn(f[p * 2 + 1]);
            hp[p] = (uint32_t)__half_as_ushort(h0) | ((uint32_t)__half_as_ushort(h1) << 16);
        }
        ((uint4*)a.h[i])[idx] = make_uint4(hp[0], hp[1], hp[2], hp[3]);
    } else {
        uint32_t hp[4], lp[4];
#pragma unroll
        for (int p = 0; p < 4; p++) {
            uint32_t hh = 0, ll = 0;
#pragma unroll
            for (int j = 0; j < 2; j++) {
                float x = f[p * 2 + j] * WSCALE;
                __half h = __float2half_rn(x);
                __half l = __float2half_rn(x - __half2float(h));
                hh |= (uint32_t)__half_as_ushort(h) << (16 * j);
                ll |= (uint32_t)__half_as_ushort(l) << (16 * j);
            }
            hp[p] = hh; lp[p] = ll;
        }
        ((uint4*)a.h[i])[idx] = make_uint4(hp[0], hp[1], hp[2], hp[3]);
        ((uint4*)a.l[i])[idx] = make_uint4(lp[0], lp[1], lp[2], lp[3]);
    }
}

// ---------------- gate pipeline (fp32, proven) ----------------
__global__ void k_zero() {
    if (threadIdx.x < E_) g_counts[threadIdx.x] = 0;
}

__global__ void k_gate(const float* __restrict__ x, const float* __restrict__ gw, int T) {
    __shared__ float sg[E_ * D_];
    const float4* gw4 = (const float4*)gw;
    float4* sg4 = (float4*)sg;
    for (int i = threadIdx.x; i < E_ * D_ / 4; i += blockDim.x) sg4[i] = gw4[i];
    __syncthreads();

    int wid = threadIdx.x >> 5, lane = threadIdx.x & 31;
    int t = blockIdx.x * 8 + wid;
    if (t >= T) return;

    float acc[E_];
#pragma unroll
    for (int e = 0; e < E_; e++) acc[e] = 0.f;
    const float4* xr = (const float4*)(x + (size_t)t * D_);
    for (int i = lane; i < D_ / 4; i += 32) {
        float4 xv = xr[i];
#pragma unroll
        for (int e = 0; e < E_; e++) {
            float4 g = sg4[e * (D_ / 4) + i];
            acc[e] += xv.x * g.x + xv.y * g.y + xv.z * g.z + xv.w * g.w;
        }
    }
#pragma unroll
    for (int e = 0; e < E_; e++)
#pragma unroll
        for (int o = 16; o > 0; o >>= 1) acc[e] += __shfl_xor_sync(0xffffffffu, acc[e], o);

    if (lane == 0) {
        float m = acc[0];
#pragma unroll
        for (int e = 1; e < E_; e++) m = fmaxf(m, acc[e]);
        float p[E_]; float s = 0.f;
#pragma unroll
        for (int e = 0; e < E_; e++) { p[e] = __expf(acc[e] - m); s += p[e]; }
        float inv = 1.f / s;
#pragma unroll
        for (int e = 0; e < E_; e++) p[e] *= inv;
        int i0 = 0; float v0 = p[0];
#pragma unroll
        for (int e = 1; e < E_; e++) if (p[e] > v0) { v0 = p[e]; i0 = e; }
        int i1 = -1; float v1 = -1.f;
#pragma unroll
        for (int e = 0; e < E_; e++) if (e != i0 && p[e] > v1) { v1 = p[e]; i1 = e; }
        g_top[t * 2] = i0;  g_top[t * 2 + 1] = i1;
        g_wgt[t * 2] = v0;  g_wgt[t * 2 + 1] = v1;
        atomicAdd(&g_counts[i0], 1);
        atomicAdd(&g_counts[i1], 1);
    }
}

__global__ void k_offs() {
    if (threadIdx.x == 0) {
        int s = 0;
        for (int e = 0; e < E_; e++) { g_offs[e] = s; s += g_counts[e]; g_cursor[e] = 0; }
        g_offs[E_] = s;
    }
}

__global__ void k_scatter(int T) {
    int i = blockIdx.x * blockDim.x + threadIdx.x;
    if (i >= T * 2) return;
    int t = i >> 1;
    int e = g_top[i];
    int pos = atomicAdd(&g_cursor[e], 1);
    int idx = g_offs[e] + pos;
    g_bucket[idx] = t;
    g_bw[idx] = g_wgt[i];
}

// ======================================================================
// fc1: fp16 2-term GEMM. C = A*(Bh+Bl), B = 256*W split hi/lo.
// CTA: 128 rows x 64 features (128 interleaved y/g weight rows).
// SiLU fused at epilogue; activations written as single fp16 plane.
// ======================================================================
template <bool ROUTED>
__global__ __launch_bounds__(256)
void k_fc1t(const __half* __restrict__ Aq, const __half* __restrict__ Whg,
            const __half* __restrict__ Wlg, __half* __restrict__ Oq,
            int T, int hid) {
    extern __shared__ __half sm[];
    __shared__ int toks[128];

    int mcount, rbase;
    const __half *Wh, *Wl;
    if (ROUTED) {
        int e = blockIdx.z;
        rbase = g_offs[e];
        mcount = g_offs[e + 1] - rbase;
        size_t wo = (size_t)e * 2 * hid * D_;
        Wh = Whg + wo; Wl = Wlg + wo;
    } else { mcount = T; rbase = 0; Wh = Whg; Wl = Wlg; }
    int m0 = blockIdx.x * 128;
    if (m0 >= mcount) return;
    int n0f = blockIdx.y * 64;
    int tid = threadIdx.x;

    if (tid < 128) {
        int r = m0 + tid; if (r > mcount - 1) r = mcount - 1;
        toks[tid] = ROUTED ? g_bucket[rbase + r] : r;
    }
    __syncthreads();

    uint32_t sbase = cvta_s(sm);
    const int K = D_;
    const int nst = K / KSZ;

    auto load_stage = [&](int s) {
        uint32_t sb = sbase + (uint32_t)(s & 1) * STAGEB;
        int k0 = s * KSZ;
#pragma unroll
        for (int j = 0; j < 6; j++) {
            int c = tid + 256 * j;
            int mat = c >> 9;             // 0=A, 1=Bh, 2=Bl
            int rc = c & 511;
            int row = rc >> 2;
            int ch = rc & 3;
            uint32_t dst = sb + (uint32_t)(mat * MATB + (row * STR + ch * 8) * 2);
            const __half* src;
            if (mat == 0) {
                src = Aq + (size_t)toks[row] * K + k0 + ch * 8;
            } else {
                int f = n0f + (row >> 1);
                int srow = (row & 1) ? (hid + f) : f;
                src = ((mat == 1) ? Wh : Wl) + (size_t)srow * K + k0 + ch * 8;
            }
            CPA(dst, src);
        }
        CPC();
    };

    int wid = tid >> 5, lane = tid & 31;
    int wm = wid >> 2, wn = wid & 3;

    float c[4][4][4];
#pragma unroll
    for (int a = 0; a < 4; a++)
#pragma unroll
        for (int b = 0; b < 4; b++)
#pragma unroll
            for (int d = 0; d < 4; d++) c[a][b][d] = 0.f;

    int arow = wm * 64 + (lane & 15);
    int acol0 = (lane >> 4) * 8;
    int g8 = lane >> 3;
    int brin = lane & 7;

    load_stage(0);
    for (int s = 0; s < nst; s++) {
        if (s + 1 < nst) { load_stage(s + 1); CPW1(); } else { CPW0(); }
        __syncthreads();
        uint32_t sb = sbase + (uint32_t)(s & 1) * STAGEB;
        uint32_t Ab  = sb;
        uint32_t Bhb = sb + MATB;
        uint32_t Blb = sb + 2 * MATB;
#pragma unroll
        for (int ks = 0; ks < 2; ks++) {
            uint32_t af[4][4], bh[4][2], bl[4][2];
#pragma unroll
            for (int mi = 0; mi < 4; mi++) {
                uint32_t off = (uint32_t)((arow + mi * 16) * STR + ks * 16 + acol0) * 2;
                LDM4(af[mi][0], af[mi][1], af[mi][2], af[mi][3], Ab + off);
            }
#pragma unroll
            for (int j2 = 0; j2 < 2; j2++) {
                int nf = j2 * 2 + (g8 >> 1);
                uint32_t off = (uint32_t)((wn * 32 + nf * 8 + brin) * STR + ks * 16 + (g8 & 1) * 8) * 2;
                uint32_t r0, r1, r2, r3;
                LDM4(r0, r1, r2, r3, Bhb + off);
                bh[j2 * 2][0] = r0; bh[j2 * 2][1] = r1; bh[j2 * 2 + 1][0] = r2; bh[j2 * 2 + 1][1] = r3;
                LDM4(r0, r1, r2, r3, Blb + off);
                bl[j2 * 2][0] = r0; bl[j2 * 2][1] = r1; bl[j2 * 2 + 1][0] = r2; bl[j2 * 2 + 1][1] = r3;
            }
            // term-major: same-accumulator reuse distance = 16 MMAs
#pragma unroll
            for (int mi = 0; mi < 4; mi++)
#pragma unroll
                for (int nj = 0; nj < 4; nj++) MMA(c[mi][nj], af[mi], bh[nj]);
#pragma unroll
            for (int mi = 0; mi < 4; mi++)
#pragma unroll
                for (int nj = 0; nj < 4; nj++) MMA(c[mi][nj], af[mi], bl[nj]);
        }
        __syncthreads();
    }

    int rrem = mcount - m0;
#pragma unroll
    for (int mi = 0; mi < 4; mi++)
#pragma unroll
        for (int half = 0; half < 2; half++) {
            int row = wm * 64 + mi * 16 + (lane >> 2) + half * 8;
            if (row < rrem) {
                size_t rb = (size_t)(rbase + m0 + row) * hid;
#pragma unroll
                for (int nj = 0; nj < 4; nj++) {
                    float y = c[mi][nj][half * 2 + 0] * INV_WSCALE;
                    float g = c[mi][nj][half * 2 + 1] * INV_WSCALE;
                    float a = y * g / (1.f + __expf(-g));
                    int f = n0f + wn * 16 + nj * 4 + (lane & 3);
                    Oq[rb + f] = __float2half_rn(a);
                }
            }
        }
}

// ======================================================================
// fc2: fp16 2-term GEMM, tile 128 x 128. C = A*(Bh+Bl), B = 256*W2.
// ROUTED -> atomicAdd * routing weight; shared -> plain store.
// ======================================================================
template <bool ROUTED>
__global__ __launch_bounds__(256)
void k_fc2t(const __half* __restrict__ Aq, const __half* __restrict__ Whg,
            const __half* __restrict__ Wlg, float* __restrict__ out,
            int T, int hid) {
    extern __shared__ __half sm[];
    __shared__ int toks[128];
    __shared__ float bws[128];

    int mcount, rbase;
    const __half *Wh, *Wl;
    if (ROUTED) {
        int e = blockIdx.z;
        rbase = g_offs[e];
        mcount = g_offs[e + 1] - rbase;
        size_t wo = (size_t)e * D_ * hid;
        Wh = Whg + wo; Wl = Wlg + wo;
    } else { mcount = T; rbase = 0; Wh = Whg; Wl = Wlg; }
    int m0 = blockIdx.x * 128;
    if (m0 >= mcount) return;
    int n0 = blockIdx.y * 128;
    int tid = threadIdx.x;

    if (ROUTED && tid < 128) {
        int r = m0 + tid; if (r > mcount - 1) r = mcount - 1;
        toks[tid] = g_bucket[rbase + r];
        bws[tid] = g_bw[rbase + r];
    }
    __syncthreads();

    uint32_t sbase = cvta_s(sm);
    const int K = hid;
    const int nst = K / KSZ;

    auto load_stage = [&](int s) {
        uint32_t sb = sbase + (uint32_t)(s & 1) * STAGEB;
        int k0 = s * KSZ;
#pragma unroll
        for (int j = 0; j < 6; j++) {
            int c = tid + 256 * j;
            int mat = c >> 9;             // 0=A, 1=Bh, 2=Bl
            int rc = c & 511;
            int row = rc >> 2;
            int ch = rc & 3;
            uint32_t dst = sb + (uint32_t)(mat * MATB + (row * STR + ch * 8) * 2);
            const __half* src;
            if (mat == 0) {
                int ar = m0 + row; if (ar > mcount - 1) ar = mcount - 1;
                src = Aq + (size_t)(rbase + ar) * K + k0 + ch * 8;
            } else {
                src = ((mat == 1) ? Wh : Wl) + (size_t)(n0 + row) * K + k0 + ch * 8;
            }
            CPA(dst, src);
        }
        CPC();
    };

    int wid = tid >> 5, lane = tid & 31;
    int wm = wid >> 2, wn = wid & 3;

    float c[4][4][4];
#pragma unroll
    for (int a = 0; a < 4; a++)
#pragma unroll
        for (int b = 0; b < 4; b++)
#pragma unroll
            for (int d = 0; d < 4; d++) c[a][b][d] = 0.f;

    int arow = wm * 64 + (lane & 15);
    int acol0 = (lane >> 4) * 8;
    int g8 = lane >> 3;
    int brin = lane & 7;

    load_stage(0);
    for (int s = 0; s < nst; s++) {
        if (s + 1 < nst) { load_stage(s + 1); CPW1(); } else { CPW0(); }
        __syncthreads();
        uint32_t sb = sbase + (uint32_t)(s & 1) * STAGEB;
        uint32_t Ab  = sb;
        uint32_t Bhb = sb + MATB;
        uint32_t Blb = sb + 2 * MATB;
#pragma unroll
        for (int ks = 0; ks < 2; ks++) {
            uint32_t af[4][4], bh[4][2], bl[4][2];
#pragma unroll
            for (int mi = 0; mi < 4; mi++) {
                uint32_t off = (uint32_t)((arow + mi * 16) * STR + ks * 16 + acol0) * 2;
                LDM4(af[mi][0], af[mi][1], af[mi][2], af[mi][3], Ab + off);
            }
#pragma unroll
            for (int j2 = 0; j2 < 2; j2++) {
                int nf = j2 * 2 + (g8 >> 1);
                uint32_t off = (uint32_t)((wn * 32 + nf * 8 + brin) * STR + ks * 16 + (g8 & 1) * 8) * 2;
                uint32_t r0, r1, r2, r3;
                LDM4(r0, r1, r2, r3, Bhb + off);
                bh[j2 * 2][0] = r0; bh[j2 * 2][1] = r1; bh[j2 * 2 + 1][0] = r2; bh[j2 * 2 + 1][1] = r3;
                LDM4(r0, r1, r2, r3, Blb + off);
                bl[j2 * 2][0] = r0; bl[j2 * 2][1] = r1; bl[j2 * 2 + 1][0] = r2; bl[j2 * 2 + 1][1] = r3;
            }
#pragma unroll
            for (int mi = 0; mi < 4; mi++)
#pragma unroll
                for (int nj = 0; nj < 4; nj++) MMA(c[mi][nj], af[mi], bh[nj]);
#pragma unroll
            for (int mi = 0; mi < 4; mi++)
#pragma unroll
                for (int nj = 0; nj < 4; nj++) MMA(c[mi][nj], af[mi], bl[nj]);
        }
        __syncthreads();
    }

    int rrem = mcount - m0;
#pragma unroll
    for (int mi = 0; mi < 4; mi++)
#pragma unroll
        for (int half = 0; half < 2; half++) {
            int row = wm * 64 + mi * 16 + (lane >> 2) + half * 8;
            if (row < rrem) {
#pragma unroll
                for (int nj = 0; nj < 4; nj++) {
                    int col = n0 + wn * 32 + nj * 8 + (lane & 3) * 2;
                    float v0 = c[mi][nj][half * 2 + 0] * INV_WSCALE;
                    float v1 = c[mi][nj][half * 2 + 1] * INV_WSCALE;
                    if (ROUTED) {
                        int t = toks[row]; float w = bws[row];
                        atomicAdd(out + (size_t)t * D_ + col, w * v0);
                        atomicAdd(out + (size_t)t * D_ + col + 1, w * v1);
                    } else {
                        *(float2*)(out + (size_t)(m0 + row) * D_ + col) = make_float2(v0, v1);
                    }
                }
            }
        }
}

// ---------------- launcher ----------------
extern "C" void kernel_launch(void* const* d_in, const int* in_sizes, int n_in,
                              void* d_out, int out_size) {
    const float* x   = (const float*)d_in[0];
    const float* gw  = (const float*)d_in[1];
    const float* W1  = (const float*)d_in[2];
    const float* W2  = (const float*)d_in[3];
    const float* Ws1 = (const float*)d_in[4];
    const float* Ws2 = (const float*)d_in[5];
    float* out = (float*)d_out;

    int T = in_sizes[0] / D_;
    if (T > TMAX) T = TMAX;

    __half *xq, *W1h, *W1l, *W2h, *W2l, *S1h, *S1l, *S2h, *S2l, *aRq, *aSq;
    cudaGetSymbolAddress((void**)&xq,  g_xq);
    cudaGetSymbolAddress((void**)&W1h, g_W1h); cudaGetSymbolAddress((void**)&W1l, g_W1l);
    cudaGetSymbolAddress((void**)&W2h, g_W2h); cudaGetSymbolAddress((void**)&W2l, g_W2l);
    cudaGetSymbolAddress((void**)&S1h, g_S1h); cudaGetSymbolAddress((void**)&S1l, g_S1l);
    cudaGetSymbolAddress((void**)&S2h, g_S2h); cudaGetSymbolAddress((void**)&S2l, g_S2l);
    cudaGetSymbolAddress((void**)&aRq, g_aRq); cudaGetSymbolAddress((void**)&aSq, g_aSq);

    cudaFuncSetAttribute(k_fc1t<true>,  cudaFuncAttributeMaxDynamicSharedMemorySize, SMEM_BYTES);
    cudaFuncSetAttribute(k_fc1t<false>, cudaFuncAttributeMaxDynamicSharedMemorySize, SMEM_BYTES);
    cudaFuncSetAttribute(k_fc2t<true>,  cudaFuncAttributeMaxDynamicSharedMemorySize, SMEM_BYTES);
    cudaFuncSetAttribute(k_fc2t<false>, cudaFuncAttributeMaxDynamicSharedMemorySize, SMEM_BYTES);

    // fused conversion (single launch): x single-plane, weights 256x hi/lo
    CvtArgs ca;
    ca.s[0] = x;   ca.h[0] = xq;  ca.l[0] = nullptr;
    ca.s[1] = W1;  ca.h[1] = W1h; ca.l[1] = W1l;
    ca.s[2] = W2;  ca.h[2] = W2h; ca.l[2] = W2l;
    ca.s[3] = Ws1; ca.h[3] = S1h; ca.l[3] = S1l;
    ca.s[4] = Ws2; ca.h[4] = S2h; ca.l[4] = S2l;
    int nb[5] = {
        (T * D_ / 8) / 256,
        (E_ * 2 * H_ * D_ / 8) / 256,
        (E_ * D_ * H_ / 8) / 256,
        (2 * HS_ * D_ / 8) / 256,
        (D_ * HS_ / 8) / 256
    };
    int cum = 0;
    for (int i = 0; i < 5; i++) { cum += nb[i]; ca.bend[i] = cum; }
    k_cvt_all<<<cum, 256>>>(ca);

    // routing
    k_zero<<<1, 32>>>();
    k_gate<<<(T + 7) / 8, 256>>>(x, gw, T);
    k_offs<<<1, 32>>>();
    k_scatter<<<(T * 2 + 255) / 256, 256>>>(T);

    int mt = (T + 127) / 128;

    // fc1: routed (hidden 768) and shared (hidden 1536)
    k_fc1t<true ><<<dim3(mt, H_  / 64, E_), 256, SMEM_BYTES>>>(xq, W1h, W1l, aRq, T, H_);
    k_fc1t<false><<<dim3(mt, HS_ / 64),     256, SMEM_BYTES>>>(xq, S1h, S1l, aSq, T, HS_);

    // fc2: shared stores first, routed atomics after (stream-ordered)
    k_fc2t<false><<<dim3(mt, D_ / 128),     256, SMEM_BYTES>>>(aSq, S2h, S2l, out, T, HS_);
    k_fc2t<true ><<<dim3(mt, D_ / 128, E_), 256, SMEM_BYTES>>>(aRq, W2h, W2l, out, T, H_);
}

// round 12
// speedup vs baseline: 3.5603x; 1.2042x over previous
#include <cuda_runtime.h>
#include <cuda_fp16.h>
#include <stdint.h>

#define D_    1024
#define H_    768
#define HS_   1536
#define E_    8
#define TMAX  2048
#define AMAX  (TMAX*2)

#define KSZ   32
#define STR   40                      // smem row stride in fp16 elems (80B, conflict-free)
#define MATB  (128*STR*2)             // 10240 B per matrix tile (128 rows x 32 elems + pad)
#define STAGEB (2*MATB)               // A, B -> 20480 B
#define SMEM_BYTES (2*STAGEB)         // 40960 B, double buffered

// ---------------- routing scratch ----------------
__device__ int   g_counts[E_];
__device__ int   g_offs[E_ + 1];
__device__ int   g_cursor[E_];
__device__ int   g_top[AMAX];
__device__ float g_wgt[AMAX];
__device__ int   g_bucket[AMAX];
__device__ float g_bw[AMAX];

// ---------------- fp16 operand scratch (single plane everywhere) ----------------
__device__ __align__(16) __half g_xq[TMAX * D_];
__device__ __align__(16) __half g_W1q[E_ * 2 * H_ * D_];
__device__ __align__(16) __half g_W2q[E_ * D_ * H_];
__device__ __align__(16) __half g_S1q[2 * HS_ * D_];
__device__ __align__(16) __half g_S2q[D_ * HS_];
__device__ __align__(16) __half g_aRq[AMAX * H_];
__device__ __align__(16) __half g_aSq[TMAX * HS_];

// ---------------- PTX helpers ----------------
__device__ __forceinline__ uint32_t cvta_s(const void* p) {
    return (uint32_t)__cvta_generic_to_shared(p);
}
#define CPA(dst, src) asm volatile("cp.async.cg.shared.global [%0], [%1], 16;\n" :: "r"(dst), "l"(src))
#define CPC() asm volatile("cp.async.commit_group;\n")
#define CPW1() asm volatile("cp.async.wait_group 1;\n")
#define CPW0() asm volatile("cp.async.wait_group 0;\n")
#define LDM4(r0, r1, r2, r3, a) \
    asm volatile("ldmatrix.sync.aligned.m8n8.x4.shared.b16 {%0,%1,%2,%3}, [%4];" \
        : "=r"(r0), "=r"(r1), "=r"(r2), "=r"(r3) : "r"(a))
#define MMA(c, a, b) \
    asm volatile("mma.sync.aligned.m16n8k16.row.col.f32.f16.f16.f32 " \
        "{%0,%1,%2,%3},{%4,%5,%6,%7},{%8,%9},{%0,%1,%2,%3};" \
        : "+f"(c[0]), "+f"(c[1]), "+f"(c[2]), "+f"(c[3]) \
        : "r"(a[0]), "r"(a[1]), "r"(a[2]), "r"(a[3]), "r"(b[0]), "r"(b[1]))

// ---------------- conversion: all five fp32 tensors -> single fp16 ----------------
struct CvtArgs {
    const float* s[5];
    __half* h[5];
    int bend[5];
};

__global__ void k_cvt_all(CvtArgs a) {
    int b = blockIdx.x;
    int i = 0;
    if (b >= a.bend[0]) i = 1;
    if (b >= a.bend[1]) i = 2;
    if (b >= a.bend[2]) i = 3;
    if (b >= a.bend[3]) i = 4;
    int lb = b - (i ? a.bend[i - 1] : 0);
    int idx = lb * 256 + threadIdx.x;          // index of 8-float chunk

    const float4* src = (const float4*)a.s[i];
    float4 v0 = src[idx * 2];
    float4 v1 = src[idx * 2 + 1];
    float f[8] = {v0.x, v0.y, v0.z, v0.w, v1.x, v1.y, v1.z, v1.w};
    uint32_t hp[4];
#pragma unroll
    for (int p = 0; p < 4; p++) {
        __half h0 = __float2half_rn(f[p * 2]);
        __half h1 = __float2half_rn(f[p * 2 + 1]);
        hp[p] = (uint32_t)__half_as_ushort(h0) | ((uint32_t)__half_as_ushort(h1) << 16);
    }
    ((uint4*)a.h[i])[idx] = make_uint4(hp[0], hp[1], hp[2], hp[3]);
}

// ---------------- gate pipeline (fp32, proven) ----------------
__global__ void k_zero() {
    if (threadIdx.x < E_) g_counts[threadIdx.x] = 0;
}

__global__ void k_gate(const float* __restrict__ x, const float* __restrict__ gw, int T) {
    __shared__ float sg[E_ * D_];
    const float4* gw4 = (const float4*)gw;
    float4* sg4 = (float4*)sg;
    for (int i = threadIdx.x; i < E_ * D_ / 4; i += blockDim.x) sg4[i] = gw4[i];
    __syncthreads();

    int wid = threadIdx.x >> 5, lane = threadIdx.x & 31;
    int t = blockIdx.x * 8 + wid;
    if (t >= T) return;

    float acc[E_];
#pragma unroll
    for (int e = 0; e < E_; e++) acc[e] = 0.f;
    const float4* xr = (const float4*)(x + (size_t)t * D_);
    for (int i = lane; i < D_ / 4; i += 32) {
        float4 xv = xr[i];
#pragma unroll
        for (int e = 0; e < E_; e++) {
            float4 g = sg4[e * (D_ / 4) + i];
            acc[e] += xv.x * g.x + xv.y * g.y + xv.z * g.z + xv.w * g.w;
        }
    }
#pragma unroll
    for (int e = 0; e < E_; e++)
#pragma unroll
        for (int o = 16; o > 0; o >>= 1) acc[e] += __shfl_xor_sync(0xffffffffu, acc[e], o);

    if (lane == 0) {
        float m = acc[0];
#pragma unroll
        for (int e = 1; e < E_; e++) m = fmaxf(m, acc[e]);
        float p[E_]; float s = 0.f;
#pragma unroll
        for (int e = 0; e < E_; e++) { p[e] = __expf(acc[e] - m); s += p[e]; }
        float inv = 1.f / s;
#pragma unroll
        for (int e = 0; e < E_; e++) p[e] *= inv;
        int i0 = 0; float v0 = p[0];
#pragma unroll
        for (int e = 1; e < E_; e++) if (p[e] > v0) { v0 = p[e]; i0 = e; }
        int i1 = -1; float v1 = -1.f;
#pragma unroll
        for (int e = 0; e < E_; e++) if (e != i0 && p[e] > v1) { v1 = p[e]; i1 = e; }
        g_top[t * 2] = i0;  g_top[t * 2 + 1] = i1;
        g_wgt[t * 2] = v0;  g_wgt[t * 2 + 1] = v1;
        atomicAdd(&g_counts[i0], 1);
        atomicAdd(&g_counts[i1], 1);
    }
}

__global__ void k_offs() {
    if (threadIdx.x == 0) {
        int s = 0;
        for (int e = 0; e < E_; e++) { g_offs[e] = s; s += g_counts[e]; g_cursor[e] = 0; }
        g_offs[E_] = s;
    }
}

__global__ void k_scatter(int T) {
    int i = blockIdx.x * blockDim.x + threadIdx.x;
    if (i >= T * 2) return;
    int t = i >> 1;
    int e = g_top[i];
    int pos = atomicAdd(&g_cursor[e], 1);
    int idx = g_offs[e] + pos;
    g_bucket[idx] = t;
    g_bw[idx] = g_wgt[i];
}

// ======================================================================
// fc1: plain fp16 GEMM. CTA: 128 rows x 64 features (128 interleaved y/g
// weight rows). SiLU fused at epilogue; acts written as fp16.
// ======================================================================
template <bool ROUTED>
__global__ __launch_bounds__(256)
void k_fc1t(const __half* __restrict__ Aq, const __half* __restrict__ Wq,
            __half* __restrict__ Oq, int T, int hid) {
    extern __shared__ __half sm[];
    __shared__ int toks[128];

    int mcount, rbase;
    const __half* W;
    if (ROUTED) {
        int e = blockIdx.z;
        rbase = g_offs[e];
        mcount = g_offs[e + 1] - rbase;
        W = Wq + (size_t)e * 2 * hid * D_;
    } else { mcount = T; rbase = 0; W = Wq; }
    int m0 = blockIdx.x * 128;
    if (m0 >= mcount) return;
    int n0f = blockIdx.y * 64;
    int tid = threadIdx.x;

    if (tid < 128) {
        int r = m0 + tid; if (r > mcount - 1) r = mcount - 1;
        toks[tid] = ROUTED ? g_bucket[rbase + r] : r;
    }
    __syncthreads();

    uint32_t sbase = cvta_s(sm);
    const int K = D_;
    const int nst = K / KSZ;

    auto load_stage = [&](int s) {
        uint32_t sb = sbase + (uint32_t)(s & 1) * STAGEB;
        int k0 = s * KSZ;
#pragma unroll
        for (int j = 0; j < 4; j++) {
            int c = tid + 256 * j;
            int mat = c >> 9;             // 0=A, 1=B
            int rc = c & 511;
            int row = rc >> 2;
            int ch = rc & 3;
            uint32_t dst = sb + (uint32_t)(mat * MATB + (row * STR + ch * 8) * 2);
            const __half* src;
            if (mat == 0) {
                src = Aq + (size_t)toks[row] * K + k0 + ch * 8;
            } else {
                int f = n0f + (row >> 1);
                int srow = (row & 1) ? (hid + f) : f;
                src = W + (size_t)srow * K + k0 + ch * 8;
            }
            CPA(dst, src);
        }
        CPC();
    };

    int wid = tid >> 5, lane = tid & 31;
    int wm = wid >> 2, wn = wid & 3;

    float c[4][4][4];
#pragma unroll
    for (int a = 0; a < 4; a++)
#pragma unroll
        for (int b = 0; b < 4; b++)
#pragma unroll
            for (int d = 0; d < 4; d++) c[a][b][d] = 0.f;

    int arow = wm * 64 + (lane & 15);
    int acol0 = (lane >> 4) * 8;
    int g8 = lane >> 3;
    int brin = lane & 7;

    load_stage(0);
    for (int s = 0; s < nst; s++) {
        if (s + 1 < nst) { load_stage(s + 1); CPW1(); } else { CPW0(); }
        __syncthreads();
        uint32_t sb = sbase + (uint32_t)(s & 1) * STAGEB;
        uint32_t Ab = sb;
        uint32_t Bb = sb + MATB;
#pragma unroll
        for (int ks = 0; ks < 2; ks++) {
            uint32_t af[4][4], bf[4][2];
#pragma unroll
            for (int mi = 0; mi < 4; mi++) {
                uint32_t off = (uint32_t)((arow + mi * 16) * STR + ks * 16 + acol0) * 2;
                LDM4(af[mi][0], af[mi][1], af[mi][2], af[mi][3], Ab + off);
            }
#pragma unroll
            for (int j2 = 0; j2 < 2; j2++) {
                int nf = j2 * 2 + (g8 >> 1);
                uint32_t off = (uint32_t)((wn * 32 + nf * 8 + brin) * STR + ks * 16 + (g8 & 1) * 8) * 2;
                uint32_t r0, r1, r2, r3;
                LDM4(r0, r1, r2, r3, Bb + off);
                bf[j2 * 2][0] = r0; bf[j2 * 2][1] = r1; bf[j2 * 2 + 1][0] = r2; bf[j2 * 2 + 1][1] = r3;
            }
#pragma unroll
            for (int mi = 0; mi < 4; mi++)
#pragma unroll
                for (int nj = 0; nj < 4; nj++) MMA(c[mi][nj], af[mi], bf[nj]);
        }
        __syncthreads();
    }

    int rrem = mcount - m0;
#pragma unroll
    for (int mi = 0; mi < 4; mi++)
#pragma unroll
        for (int half = 0; half < 2; half++) {
            int row = wm * 64 + mi * 16 + (lane >> 2) + half * 8;
            if (row < rrem) {
                size_t rb = (size_t)(rbase + m0 + row) * hid;
#pragma unroll
                for (int nj = 0; nj < 4; nj++) {
                    float y = c[mi][nj][half * 2 + 0];
                    float g = c[mi][nj][half * 2 + 1];
                    float a = y * g / (1.f + __expf(-g));
                    int f = n0f + wn * 16 + nj * 4 + (lane & 3);
                    Oq[rb + f] = __float2half_rn(a);
                }
            }
        }
}

// ======================================================================
// fc2: plain fp16 GEMM, tile 128 x 128.
// ROUTED -> atomicAdd * routing weight; shared -> plain store.
// ======================================================================
template <bool ROUTED>
__global__ __launch_bounds__(256)
void k_fc2t(const __half* __restrict__ Aq, const __half* __restrict__ Wq,
            float* __restrict__ out, int T, int hid) {
    extern __shared__ __half sm[];
    __shared__ int toks[128];
    __shared__ float bws[128];

    int mcount, rbase;
    const __half* W;
    if (ROUTED) {
        int e = blockIdx.z;
        rbase = g_offs[e];
        mcount = g_offs[e + 1] - rbase;
        W = Wq + (size_t)e * D_ * hid;
    } else { mcount = T; rbase = 0; W = Wq; }
    int m0 = blockIdx.x * 128;
    if (m0 >= mcount) return;
    int n0 = blockIdx.y * 128;
    int tid = threadIdx.x;

    if (ROUTED && tid < 128) {
        int r = m0 + tid; if (r > mcount - 1) r = mcount - 1;
        toks[tid] = g_bucket[rbase + r];
        bws[tid] = g_bw[rbase + r];
    }
    __syncthreads();

    uint32_t sbase = cvta_s(sm);
    const int K = hid;
    const int nst = K / KSZ;

    auto load_stage = [&](int s) {
        uint32_t sb = sbase + (uint32_t)(s & 1) * STAGEB;
        int k0 = s * KSZ;
#pragma unroll
        for (int j = 0; j < 4; j++) {
            int c = tid + 256 * j;
            int mat = c >> 9;             // 0=A, 1=B
            int rc = c & 511;
            int row = rc >> 2;
            int ch = rc & 3;
            uint32_t dst = sb + (uint32_t)(mat * MATB + (row * STR + ch * 8) * 2);
            const __half* src;
            if (mat == 0) {
                int ar = m0 + row; if (ar > mcount - 1) ar = mcount - 1;
                src = Aq + (size_t)(rbase + ar) * K + k0 + ch * 8;
            } else {
                src = W + (size_t)(n0 + row) * K + k0 + ch * 8;
            }
            CPA(dst, src);
        }
        CPC();
    };

    int wid = tid >> 5, lane = tid & 31;
    int wm = wid >> 2, wn = wid & 3;

    float c[4][4][4];
#pragma unroll
    for (int a = 0; a < 4; a++)
#pragma unroll
        for (int b = 0; b < 4; b++)
#pragma unroll
            for (int d = 0; d < 4; d++) c[a][b][d] = 0.f;

    int arow = wm * 64 + (lane & 15);
    int acol0 = (lane >> 4) * 8;
    int g8 = lane >> 3;
    int brin = lane & 7;

    load_stage(0);
    for (int s = 0; s < nst; s++) {
        if (s + 1 < nst) { load_stage(s + 1); CPW1(); } else { CPW0(); }
        __syncthreads();
        uint32_t sb = sbase + (uint32_t)(s & 1) * STAGEB;
        uint32_t Ab = sb;
        uint32_t Bb = sb + MATB;
#pragma unroll
        for (int ks = 0; ks < 2; ks++) {
            uint32_t af[4][4], bf[4][2];
#pragma unroll
            for (int mi = 0; mi < 4; mi++) {
                uint32_t off = (uint32_t)((arow + mi * 16) * STR + ks * 16 + acol0) * 2;
                LDM4(af[mi][0], af[mi][1], af[mi][2], af[mi][3], Ab + off);
            }
#pragma unroll
            for (int j2 = 0; j2 < 2; j2++) {
                int nf = j2 * 2 + (g8 >> 1);
                uint32_t off = (uint32_t)((wn * 32 + nf * 8 + brin) * STR + ks * 16 + (g8 & 1) * 8) * 2;
                uint32_t r0, r1, r2, r3;
                LDM4(r0, r1, r2, r3, Bb + off);
                bf[j2 * 2][0] = r0; bf[j2 * 2][1] = r1; bf[j2 * 2 + 1][0] = r2; bf[j2 * 2 + 1][1] = r3;
            }
#pragma unroll
            for (int mi = 0; mi < 4; mi++)
#pragma unroll
                for (int nj = 0; nj < 4; nj++) MMA(c[mi][nj], af[mi], bf[nj]);
        }
        __syncthreads();
    }

    int rrem = mcount - m0;
#pragma unroll
    for (int mi = 0; mi < 4; mi++)
#pragma unroll
        for (int half = 0; half < 2; half++) {
            int row = wm * 64 + mi * 16 + (lane >> 2) + half * 8;
            if (row < rrem) {
#pragma unroll
                for (int nj = 0; nj < 4; nj++) {
                    int col = n0 + wn * 32 + nj * 8 + (lane & 3) * 2;
                    float v0 = c[mi][nj][half * 2 + 0];
                    float v1 = c[mi][nj][half * 2 + 1];
                    if (ROUTED) {
                        int t = toks[row]; float w = bws[row];
                        atomicAdd(out + (size_t)t * D_ + col, w * v0);
                        atomicAdd(out + (size_t)t * D_ + col + 1, w * v1);
                    } else {
                        *(float2*)(out + (size_t)(m0 + row) * D_ + col) = make_float2(v0, v1);
                    }
                }
            }
        }
}

// ---------------- launcher ----------------
extern "C" void kernel_launch(void* const* d_in, const int* in_sizes, int n_in,
                              void* d_out, int out_size) {
    const float* x   = (const float*)d_in[0];
    const float* gw  = (const float*)d_in[1];
    const float* W1  = (const float*)d_in[2];
    const float* W2  = (const float*)d_in[3];
    const float* Ws1 = (const float*)d_in[4];
    const float* Ws2 = (const float*)d_in[5];
    float* out = (float*)d_out;

    int T = in_sizes[0] / D_;
    if (T > TMAX) T = TMAX;

    __half *xq, *W1q, *W2q, *S1q, *S2q, *aRq, *aSq;
    cudaGetSymbolAddress((void**)&xq,  g_xq);
    cudaGetSymbolAddress((void**)&W1q, g_W1q);
    cudaGetSymbolAddress((void**)&W2q, g_W2q);
    cudaGetSymbolAddress((void**)&S1q, g_S1q);
    cudaGetSymbolAddress((void**)&S2q, g_S2q);
    cudaGetSymbolAddress((void**)&aRq, g_aRq);
    cudaGetSymbolAddress((void**)&aSq, g_aSq);

    cudaFuncSetAttribute(k_fc1t<true>,  cudaFuncAttributeMaxDynamicSharedMemorySize, SMEM_BYTES);
    cudaFuncSetAttribute(k_fc1t<false>, cudaFuncAttributeMaxDynamicSharedMemorySize, SMEM_BYTES);
    cudaFuncSetAttribute(k_fc2t<true>,  cudaFuncAttributeMaxDynamicSharedMemorySize, SMEM_BYTES);
    cudaFuncSetAttribute(k_fc2t<false>, cudaFuncAttributeMaxDynamicSharedMemorySize, SMEM_BYTES);

    // fused conversion (single launch): everything single-plane fp16
    CvtArgs ca;
    ca.s[0] = x;   ca.h[0] = xq;
    ca.s[1] = W1;  ca.h[1] = W1q;
    ca.s[2] = W2;  ca.h[2] = W2q;
    ca.s[3] = Ws1; ca.h[3] = S1q;
    ca.s[4] = Ws2; ca.h[4] = S2q;
    int nb[5] = {
        (T * D_ / 8) / 256,
        (E_ * 2 * H_ * D_ / 8) / 256,
        (E_ * D_ * H_ / 8) / 256,
        (2 * HS_ * D_ / 8) / 256,
        (D_ * HS_ / 8) / 256
    };
    int cum = 0;
    for (int i = 0; i < 5; i++) { cum += nb[i]; ca.bend[i] = cum; }
    k_cvt_all<<<cum, 256>>>(ca);

    // routing
    k_zero<<<1, 32>>>();
    k_gate<<<(T + 7) / 8, 256>>>(x, gw, T);
    k_offs<<<1, 32>>>();
    k_scatter<<<(T * 2 + 255) / 256, 256>>>(T);

    int mt = (T + 127) / 128;

    // fc1: routed (hidden 768) and shared (hidden 1536)
    k_fc1t<true ><<<dim3(mt, H_  / 64, E_), 256, SMEM_BYTES>>>(xq, W1q, aRq, T, H_);
    k_fc1t<false><<<dim3(mt, HS_ / 64),     256, SMEM_BYTES>>>(xq, S1q, aSq, T, HS_);

    // fc2: shared stores first, routed atomics after (stream-ordered)
    k_fc2t<false><<<dim3(mt, D_ / 128),     256, SMEM_BYTES>>>(aSq, S2q, out, T, HS_);
    k_fc2t<true ><<<dim3(mt, D_ / 128, E_), 256, SMEM_BYTES>>>(aRq, W2q, out, T, H_);
}

// round 13
// speedup vs baseline: 3.7137x; 1.0431x over previous
#include <cuda_runtime.h>
#include <cuda_fp16.h>
#include <stdint.h>

#define D_    1024
#define H_    768
#define HS_   1536
#define E_    8
#define TMAX  2048
#define AMAX  (TMAX*2)

#define KSZ   32
#define STR   40                      // smem row stride in fp16 elems (80B, conflict-free)
#define MATB  (128*STR*2)             // 10240 B per matrix tile
#define STAGEB (2*MATB)               // A, B -> 20480 B
#define SMEM_BYTES (2*STAGEB)         // 40960 B, double buffered

// ---------------- routing scratch ----------------
__device__ int   g_counts[E_];
__device__ int   g_offs[E_ + 1];
__device__ int   g_cursor[E_];
__device__ int   g_top[AMAX];
__device__ float g_wgt[AMAX];
__device__ int   g_bucket[AMAX];
__device__ float g_bw[AMAX];

// ---------------- fp16 operand scratch ----------------
__device__ __align__(16) __half g_xq[TMAX * D_];
__device__ __align__(16) __half g_W1q[E_ * 2 * H_ * D_];
__device__ __align__(16) __half g_W2q[E_ * D_ * H_];
__device__ __align__(16) __half g_S1q[2 * HS_ * D_];
__device__ __align__(16) __half g_S2q[D_ * HS_];
__device__ __align__(16) __half g_aRq[AMAX * H_];
__device__ __align__(16) __half g_aSq[TMAX * HS_];

// ---------------- PTX helpers ----------------
__device__ __forceinline__ uint32_t cvta_s(const void* p) {
    return (uint32_t)__cvta_generic_to_shared(p);
}
#define CPA(dst, src) asm volatile("cp.async.cg.shared.global [%0], [%1], 16;\n" :: "r"(dst), "l"(src))
#define CPC() asm volatile("cp.async.commit_group;\n")
#define CPW1() asm volatile("cp.async.wait_group 1;\n")
#define CPW0() asm volatile("cp.async.wait_group 0;\n")
#define LDM4(r0, r1, r2, r3, a) \
    asm volatile("ldmatrix.sync.aligned.m8n8.x4.shared.b16 {%0,%1,%2,%3}, [%4];" \
        : "=r"(r0), "=r"(r1), "=r"(r2), "=r"(r3) : "r"(a))
#define MMA(c, a, b) \
    asm volatile("mma.sync.aligned.m16n8k16.row.col.f32.f16.f16.f32 " \
        "{%0,%1,%2,%3},{%4,%5,%6,%7},{%8,%9},{%0,%1,%2,%3};" \
        : "+f"(c[0]), "+f"(c[1]), "+f"(c[2]), "+f"(c[3]) \
        : "r"(a[0]), "r"(a[1]), "r"(a[2]), "r"(a[3]), "r"(b[0]), "r"(b[1]))

// ---------------- fused conversion + counter zero + output zero ----------------
struct CvtArgs {
    const float* s[5];
    __half* h[5];
    float* outz;
    int bend[6];   // 5 cvt regions + 1 zero region (cumulative block bounds)
};

__global__ void k_cvt_all(CvtArgs a) {
    if (blockIdx.x == 0 && threadIdx.x < 2 * E_) {
        if (threadIdx.x < E_) g_counts[threadIdx.x] = 0;
        else                  g_cursor[threadIdx.x - E_] = 0;
    }
    int b = blockIdx.x;
    int i = 0;
    while (i < 5 && b >= a.bend[i]) i++;
    int lb = b - (i ? a.bend[i - 1] : 0);
    int idx = lb * 256 + threadIdx.x;          // index of 8-elem chunk

    if (i == 5) {                               // zero the output buffer
        float4 z = make_float4(0.f, 0.f, 0.f, 0.f);
        ((float4*)a.outz)[idx * 2] = z;
        ((float4*)a.outz)[idx * 2 + 1] = z;
        return;
    }

    const float4* src = (const float4*)a.s[i];
    float4 v0 = src[idx * 2];
    float4 v1 = src[idx * 2 + 1];
    float f[8] = {v0.x, v0.y, v0.z, v0.w, v1.x, v1.y, v1.z, v1.w};
    uint32_t hp[4];
#pragma unroll
    for (int p = 0; p < 4; p++) {
        __half h0 = __float2half_rn(f[p * 2]);
        __half h1 = __float2half_rn(f[p * 2 + 1]);
        hp[p] = (uint32_t)__half_as_ushort(h0) | ((uint32_t)__half_as_ushort(h1) << 16);
    }
    ((uint4*)a.h[i])[idx] = make_uint4(hp[0], hp[1], hp[2], hp[3]);
}

// ---------------- gate (fp32, proven) ----------------
__global__ void k_gate(const float* __restrict__ x, const float* __restrict__ gw, int T) {
    __shared__ float sg[E_ * D_];
    const float4* gw4 = (const float4*)gw;
    float4* sg4 = (float4*)sg;
    for (int i = threadIdx.x; i < E_ * D_ / 4; i += blockDim.x) sg4[i] = gw4[i];
    __syncthreads();

    int wid = threadIdx.x >> 5, lane = threadIdx.x & 31;
    int t = blockIdx.x * 8 + wid;
    if (t >= T) return;

    float acc[E_];
#pragma unroll
    for (int e = 0; e < E_; e++) acc[e] = 0.f;
    const float4* xr = (const float4*)(x + (size_t)t * D_);
    for (int i = lane; i < D_ / 4; i += 32) {
        float4 xv = xr[i];
#pragma unroll
        for (int e = 0; e < E_; e++) {
            float4 g = sg4[e * (D_ / 4) + i];
            acc[e] += xv.x * g.x + xv.y * g.y + xv.z * g.z + xv.w * g.w;
        }
    }
#pragma unroll
    for (int e = 0; e < E_; e++)
#pragma unroll
        for (int o = 16; o > 0; o >>= 1) acc[e] += __shfl_xor_sync(0xffffffffu, acc[e], o);

    if (lane == 0) {
        float m = acc[0];
#pragma unroll
        for (int e = 1; e < E_; e++) m = fmaxf(m, acc[e]);
        float p[E_]; float s = 0.f;
#pragma unroll
        for (int e = 0; e < E_; e++) { p[e] = __expf(acc[e] - m); s += p[e]; }
        float inv = 1.f / s;
#pragma unroll
        for (int e = 0; e < E_; e++) p[e] *= inv;
        int i0 = 0; float v0 = p[0];
#pragma unroll
        for (int e = 1; e < E_; e++) if (p[e] > v0) { v0 = p[e]; i0 = e; }
        int i1 = -1; float v1 = -1.f;
#pragma unroll
        for (int e = 0; e < E_; e++) if (e != i0 && p[e] > v1) { v1 = p[e]; i1 = e; }
        g_top[t * 2] = i0;  g_top[t * 2 + 1] = i1;
        g_wgt[t * 2] = v0;  g_wgt[t * 2 + 1] = v1;
        atomicAdd(&g_counts[i0], 1);
        atomicAdd(&g_counts[i1], 1);
    }
}

// ---------------- scatter + offsets (fused) ----------------
__global__ void k_scatter(int T) {
    int i = blockIdx.x * blockDim.x + threadIdx.x;
    if (blockIdx.x == 0 && threadIdx.x == 0) {
        int s = 0;
        for (int e = 0; e < E_; e++) { g_offs[e] = s; s += g_counts[e]; }
        g_offs[E_] = s;
    }
    if (i >= T * 2) return;
    int t = i >> 1;
    int e = g_top[i];
    int off = 0;
#pragma unroll
    for (int j = 0; j < E_; j++) off += (j < e) ? g_counts[j] : 0;
    int pos = atomicAdd(&g_cursor[e], 1);
    g_bucket[off + pos] = t;
    g_bw[off + pos] = g_wgt[i];
}

// ======================================================================
// fc1 merged (routed + shared): plain fp16 GEMM. CTA: 128 rows x 64
// features (128 interleaved y/g weight rows). SiLU fused; acts -> fp16.
// grid.y: [0,24) shared (HS tiles); [24,120) routed (e=(zy-24)/12).
// ======================================================================
__global__ __launch_bounds__(256)
void k_fc1(const __half* __restrict__ xq, const __half* __restrict__ W1q,
           const __half* __restrict__ S1q, __half* __restrict__ aRq,
           __half* __restrict__ aSq, int T) {
    extern __shared__ __half sm[];
    __shared__ int toks[128];

    int zy = blockIdx.y;
    bool routed = zy >= 24;
    int e = routed ? (zy - 24) / 12 : 0;
    int ytile = routed ? (zy - 24) % 12 : zy;
    int hid = routed ? H_ : HS_;
    const __half* W = routed ? W1q + (size_t)e * 2 * H_ * D_ : S1q;
    __half* Oq = routed ? aRq : aSq;
    int rbase = routed ? g_offs[e] : 0;
    int mcount = routed ? (g_offs[e + 1] - rbase) : T;
    int m0 = blockIdx.x * 128;
    if (m0 >= mcount) return;
    int n0f = ytile * 64;
    int tid = threadIdx.x;

    if (tid < 128) {
        int r = m0 + tid; if (r > mcount - 1) r = mcount - 1;
        toks[tid] = routed ? g_bucket[rbase + r] : r;
    }
    __syncthreads();

    uint32_t sbase = cvta_s(sm);
    const int K = D_;
    const int nst = K / KSZ;

    auto load_stage = [&](int s) {
        uint32_t sb = sbase + (uint32_t)(s & 1) * STAGEB;
        int k0 = s * KSZ;
#pragma unroll
        for (int j = 0; j < 4; j++) {
            int c = tid + 256 * j;
            int mat = c >> 9;             // 0=A, 1=B
            int rc = c & 511;
            int row = rc >> 2;
            int ch = rc & 3;
            uint32_t dst = sb + (uint32_t)(mat * MATB + (row * STR + ch * 8) * 2);
            const __half* src;
            if (mat == 0) {
                src = xq + (size_t)toks[row] * K + k0 + ch * 8;
            } else {
                int f = n0f + (row >> 1);
                int srow = (row & 1) ? (hid + f) : f;
                src = W + (size_t)srow * K + k0 + ch * 8;
            }
            CPA(dst, src);
        }
        CPC();
    };

    int wid = tid >> 5, lane = tid & 31;
    int wm = wid >> 2, wn = wid & 3;

    float c[4][4][4];
#pragma unroll
    for (int a = 0; a < 4; a++)
#pragma unroll
        for (int b = 0; b < 4; b++)
#pragma unroll
            for (int d = 0; d < 4; d++) c[a][b][d] = 0.f;

    int arow = wm * 64 + (lane & 15);
    int acol0 = (lane >> 4) * 8;
    int g8 = lane >> 3;
    int brin = lane & 7;

    load_stage(0);
    for (int s = 0; s < nst; s++) {
        if (s + 1 < nst) { load_stage(s + 1); CPW1(); } else { CPW0(); }
        __syncthreads();
        uint32_t sb = sbase + (uint32_t)(s & 1) * STAGEB;
        uint32_t Ab = sb;
        uint32_t Bb = sb + MATB;
#pragma unroll
        for (int ks = 0; ks < 2; ks++) {
            uint32_t af[4][4], bf[4][2];
#pragma unroll
            for (int mi = 0; mi < 4; mi++) {
                uint32_t off = (uint32_t)((arow + mi * 16) * STR + ks * 16 + acol0) * 2;
                LDM4(af[mi][0], af[mi][1], af[mi][2], af[mi][3], Ab + off);
            }
#pragma unroll
            for (int j2 = 0; j2 < 2; j2++) {
                int nf = j2 * 2 + (g8 >> 1);
                uint32_t off = (uint32_t)((wn * 32 + nf * 8 + brin) * STR + ks * 16 + (g8 & 1) * 8) * 2;
                uint32_t r0, r1, r2, r3;
                LDM4(r0, r1, r2, r3, Bb + off);
                bf[j2 * 2][0] = r0; bf[j2 * 2][1] = r1; bf[j2 * 2 + 1][0] = r2; bf[j2 * 2 + 1][1] = r3;
            }
#pragma unroll
            for (int mi = 0; mi < 4; mi++)
#pragma unroll
                for (int nj = 0; nj < 4; nj++) MMA(c[mi][nj], af[mi], bf[nj]);
        }
        __syncthreads();
    }

    int rrem = mcount - m0;
#pragma unroll
    for (int mi = 0; mi < 4; mi++)
#pragma unroll
        for (int half = 0; half < 2; half++) {
            int row = wm * 64 + mi * 16 + (lane >> 2) + half * 8;
            if (row < rrem) {
                size_t rb = (size_t)(rbase + m0 + row) * hid;
#pragma unroll
                for (int nj = 0; nj < 4; nj++) {
                    float y = c[mi][nj][half * 2 + 0];
                    float g = c[mi][nj][half * 2 + 1];
                    float a = y * g / (1.f + __expf(-g));
                    int f = n0f + wn * 16 + nj * 4 + (lane & 3);
                    Oq[rb + f] = __float2half_rn(a);
                }
            }
        }
}

// ======================================================================
// fc2 merged (shared z=0 first, routed z=1..8): fp16 GEMM tile 128x128.
// Output pre-zeroed; BOTH paths atomicAdd (shared with weight 1).
// ======================================================================
__global__ __launch_bounds__(256)
void k_fc2(const __half* __restrict__ aRq, const __half* __restrict__ aSq,
           const __half* __restrict__ W2q, const __half* __restrict__ S2q,
           float* __restrict__ out, int T) {
    extern __shared__ __half sm[];
    __shared__ int   toks[128];
    __shared__ int   etok[128];
    __shared__ float ew[128];

    int z = blockIdx.z;
    bool routed = z >= 1;
    int e = routed ? z - 1 : 0;
    int K = routed ? H_ : HS_;
    const __half* A = routed ? aRq : aSq;
    const __half* W = routed ? W2q + (size_t)e * D_ * H_ : S2q;
    int rbase = routed ? g_offs[e] : 0;
    int mcount = routed ? (g_offs[e + 1] - rbase) : T;
    int m0 = blockIdx.x * 128;
    if (m0 >= mcount) return;
    int n0 = blockIdx.y * 128;
    int tid = threadIdx.x;

    if (tid < 128) {
        int r = m0 + tid; if (r > mcount - 1) r = mcount - 1;
        toks[tid] = rbase + r;
        if (routed) { etok[tid] = g_bucket[rbase + r]; ew[tid] = g_bw[rbase + r]; }
        else        { etok[tid] = r;                   ew[tid] = 1.f; }
    }
    __syncthreads();

    uint32_t sbase = cvta_s(sm);
    const int nst = K / KSZ;

    auto load_stage = [&](int s) {
        uint32_t sb = sbase + (uint32_t)(s & 1) * STAGEB;
        int k0 = s * KSZ;
#pragma unroll
        for (int j = 0; j < 4; j++) {
            int c = tid + 256 * j;
            int mat = c >> 9;             // 0=A, 1=B
            int rc = c & 511;
            int row = rc >> 2;
            int ch = rc & 3;
            uint32_t dst = sb + (uint32_t)(mat * MATB + (row * STR + ch * 8) * 2);
            const __half* src;
            if (mat == 0) {
                src = A + (size_t)toks[row] * K + k0 + ch * 8;
            } else {
                src = W + (size_t)(n0 + row) * K + k0 + ch * 8;
            }
            CPA(dst, src);
        }
        CPC();
    };

    int wid = tid >> 5, lane = tid & 31;
    int wm = wid >> 2, wn = wid & 3;

    float c[4][4][4];
#pragma unroll
    for (int a = 0; a < 4; a++)
#pragma unroll
        for (int b = 0; b < 4; b++)
#pragma unroll
            for (int d = 0; d < 4; d++) c[a][b][d] = 0.f;

    int arow = wm * 64 + (lane & 15);
    int acol0 = (lane >> 4) * 8;
    int g8 = lane >> 3;
    int brin = lane & 7;

    load_stage(0);
    for (int s = 0; s < nst; s++) {
        if (s + 1 < nst) { load_stage(s + 1); CPW1(); } else { CPW0(); }
        __syncthreads();
        uint32_t sb = sbase + (uint32_t)(s & 1) * STAGEB;
        uint32_t Ab = sb;
        uint32_t Bb = sb + MATB;
#pragma unroll
        for (int ks = 0; ks < 2; ks++) {
            uint32_t af[4][4], bf[4][2];
#pragma unroll
            for (int mi = 0; mi < 4; mi++) {
                uint32_t off = (uint32_t)((arow + mi * 16) * STR + ks * 16 + acol0) * 2;
                LDM4(af[mi][0], af[mi][1], af[mi][2], af[mi][3], Ab + off);
            }
#pragma unroll
            for (int j2 = 0; j2 < 2; j2++) {
                int nf = j2 * 2 + (g8 >> 1);
                uint32_t off = (uint32_t)((wn * 32 + nf * 8 + brin) * STR + ks * 16 + (g8 & 1) * 8) * 2;
                uint32_t r0, r1, r2, r3;
                LDM4(r0, r1, r2, r3, Bb + off);
                bf[j2 * 2][0] = r0; bf[j2 * 2][1] = r1; bf[j2 * 2 + 1][0] = r2; bf[j2 * 2 + 1][1] = r3;
            }
#pragma unroll
            for (int mi = 0; mi < 4; mi++)
#pragma unroll
                for (int nj = 0; nj < 4; nj++) MMA(c[mi][nj], af[mi], bf[nj]);
        }
        __syncthreads();
    }

    int rrem = mcount - m0;
#pragma unroll
    for (int mi = 0; mi < 4; mi++)
#pragma unroll
        for (int half = 0; half < 2; half++) {
            int row = wm * 64 + mi * 16 + (lane >> 2) + half * 8;
            if (row < rrem) {
                int t = etok[row]; float w = ew[row];
                float* base = out + (size_t)t * D_;
#pragma unroll
                for (int nj = 0; nj < 4; nj++) {
                    int col = n0 + wn * 32 + nj * 8 + (lane & 3) * 2;
                    atomicAdd(base + col,     w * c[mi][nj][half * 2 + 0]);
                    atomicAdd(base + col + 1, w * c[mi][nj][half * 2 + 1]);
                }
            }
        }
}

// ---------------- launcher ----------------
extern "C" void kernel_launch(void* const* d_in, const int* in_sizes, int n_in,
                              void* d_out, int out_size) {
    const float* x   = (const float*)d_in[0];
    const float* gw  = (const float*)d_in[1];
    const float* W1  = (const float*)d_in[2];
    const float* W2  = (const float*)d_in[3];
    const float* Ws1 = (const float*)d_in[4];
    const float* Ws2 = (const float*)d_in[5];
    float* out = (float*)d_out;

    int T = in_sizes[0] / D_;
    if (T > TMAX) T = TMAX;

    __half *xq, *W1q, *W2q, *S1q, *S2q, *aRq, *aSq;
    cudaGetSymbolAddress((void**)&xq,  g_xq);
    cudaGetSymbolAddress((void**)&W1q, g_W1q);
    cudaGetSymbolAddress((void**)&W2q, g_W2q);
    cudaGetSymbolAddress((void**)&S1q, g_S1q);
    cudaGetSymbolAddress((void**)&S2q, g_S2q);
    cudaGetSymbolAddress((void**)&aRq, g_aRq);
    cudaGetSymbolAddress((void**)&aSq, g_aSq);

    cudaFuncSetAttribute(k_fc1, cudaFuncAttributeMaxDynamicSharedMemorySize, SMEM_BYTES);
    cudaFuncSetAttribute(k_fc2, cudaFuncAttributeMaxDynamicSharedMemorySize, SMEM_BYTES);

    // fused conversion + counter zero + output zero (single launch)
    CvtArgs ca;
    ca.s[0] = x;   ca.h[0] = xq;
    ca.s[1] = W1;  ca.h[1] = W1q;
    ca.s[2] = W2;  ca.h[2] = W2q;
    ca.s[3] = Ws1; ca.h[3] = S1q;
    ca.s[4] = Ws2; ca.h[4] = S2q;
    ca.outz = out;
    int nb[6] = {
        (T * D_ / 8) / 256,
        (E_ * 2 * H_ * D_ / 8) / 256,
        (E_ * D_ * H_ / 8) / 256,
        (2 * HS_ * D_ / 8) / 256,
        (D_ * HS_ / 8) / 256,
        (T * D_ / 8) / 256            // output zeroing region
    };
    int cum = 0;
    for (int i = 0; i < 6; i++) { cum += nb[i]; ca.bend[i] = cum; }
    k_cvt_all<<<cum, 256>>>(ca);

    // routing: gate, then scatter (offsets fused into scatter)
    k_gate<<<(T + 7) / 8, 256>>>(x, gw, T);
    k_scatter<<<(T * 2 + 255) / 256, 256>>>(T);

    int mt = (T + 127) / 128;

    // fc1 merged: 24 shared tiles + 96 routed tiles in one launch
    k_fc1<<<dim3(mt, 120), 256, SMEM_BYTES>>>(xq, W1q, S1q, aRq, aSq, T);

    // fc2 merged: shared (z=0, scheduled first) + routed (z=1..8)
    k_fc2<<<dim3(mt, D_ / 128, 1 + E_), 256, SMEM_BYTES>>>(aRq, aSq, W2q, S2q, out, T);
}